// round 4
// baseline (speedup 1.0000x reference)
#include <cuda_runtime.h>
#include <math.h>

#define Dm 512
#define Lm 2048
#define BATCH 2
#define NLAYER 4
#define Pm 8
#define Vm 32000
#define NT (BATCH*Lm)   /* 4096 tokens */
#define NCH 16
#define CHL (Lm/NCH)    /* 128 */

/* ---------------- scratch (no allocation allowed) ---------------- */
__device__ float g_h  [NT*Dm];
__device__ float g_hn [NT*Dm];
__device__ float g_rn [NT*Dm];
__device__ float g_val[NT*Dm];
__device__ float g_ret[NT*Dm];
__device__ float g_coef[NT];
__device__ float g_csum[BATCH*NCH*Dm];

/* ---------------- helpers ---------------- */
__device__ __forceinline__ float warp_sum(float v) {
#pragma unroll
    for (int o = 16; o > 0; o >>= 1) v += __shfl_down_sync(0xffffffffu, v, o);
    return v;
}

__device__ __forceinline__ float softplusf(float x) {
    return (x > 20.f) ? x : log1pf(expf(x));
}

/* ---------------- embedding gather ---------------- */
__global__ void embed_kernel(const int* __restrict__ tok,
                             const float* __restrict__ emb,
                             float* __restrict__ h) {
    const int t = blockIdx.x;
    const int tk = tok[t];
    const float4* s = (const float4*)(emb + (long)tk * Dm);
    float4* d = (float4*)(h + (long)t * Dm);
    d[threadIdx.x] = s[threadIdx.x];       /* 128 threads x float4 = 512 */
}

/* ---------------- LayerNorm (+ optional fused phase/amp coef) ----------------
 * one block per token, 256 threads, 2 dims per thread                      */
__global__ void __launch_bounds__(256) ln_kernel(
    const float* __restrict__ X, float* __restrict__ Y,
    const float* __restrict__ gamma, const float* __restrict__ beta,
    const float* __restrict__ pW, const float* __restrict__ pb,
    const float* __restrict__ aW, const float* __restrict__ ab,
    float* __restrict__ coef, int docoef)
{
    const int t = blockIdx.x;
    const int tid = threadIdx.x;
    const int w = tid >> 5, lane = tid & 31;

    const float2 v = ((const float2*)(X + (long)t * Dm))[tid];
    float s  = v.x + v.y;
    float ss = v.x * v.x + v.y * v.y;

    __shared__ float sred[2][8];
    __shared__ float smean, sinv;
    float ws = warp_sum(s), wss = warp_sum(ss);
    if (lane == 0) { sred[0][w] = ws; sred[1][w] = wss; }
    __syncthreads();
    if (tid == 0) {
        float S = 0.f, SS = 0.f;
#pragma unroll
        for (int i = 0; i < 8; i++) { S += sred[0][i]; SS += sred[1][i]; }
        const float m = S * (1.f / Dm);
        const float var = SS * (1.f / Dm) - m * m;
        smean = m; sinv = rsqrtf(var + 1e-5f);
    }
    __syncthreads();
    const float m = smean, inv = sinv;
    const int d0 = tid * 2;
    const float y0 = (v.x - m) * inv * gamma[d0]     + beta[d0];
    const float y1 = (v.y - m) * inv * gamma[d0 + 1] + beta[d0 + 1];
    ((float2*)(Y + (long)t * Dm))[tid] = make_float2(y0, y1);

    if (docoef) {
        float pa[8], aa[8];
#pragma unroll
        for (int j = 0; j < 8; j++) { pa[j] = 0.f; aa[j] = 0.f; }
        const float4* pw4 = (const float4*)(pW + (long)d0 * Pm);
        const float4* aw4 = (const float4*)(aW + (long)d0 * Pm);
        const float ys[2] = { y0, y1 };
#pragma unroll
        for (int dd = 0; dd < 2; dd++) {
            const float yv = ys[dd];
            float4 w0 = pw4[dd * 2], w1 = pw4[dd * 2 + 1];
            pa[0] += yv * w0.x; pa[1] += yv * w0.y; pa[2] += yv * w0.z; pa[3] += yv * w0.w;
            pa[4] += yv * w1.x; pa[5] += yv * w1.y; pa[6] += yv * w1.z; pa[7] += yv * w1.w;
            w0 = aw4[dd * 2]; w1 = aw4[dd * 2 + 1];
            aa[0] += yv * w0.x; aa[1] += yv * w0.y; aa[2] += yv * w0.z; aa[3] += yv * w0.w;
            aa[4] += yv * w1.x; aa[5] += yv * w1.y; aa[6] += yv * w1.z; aa[7] += yv * w1.w;
        }
        __shared__ float red16[16][8];
#pragma unroll
        for (int j = 0; j < 8; j++) {
            float r = warp_sum(pa[j]); if (lane == 0) red16[j][w] = r;
            r = warp_sum(aa[j]);       if (lane == 0) red16[8 + j][w] = r;
        }
        __syncthreads();
        if (tid < 16) {
            float r = 0.f;
#pragma unroll
            for (int i = 0; i < 8; i++) r += red16[tid][i];
            red16[tid][0] = r;
        }
        __syncthreads();
        if (tid == 0) {
            float c = 0.f;
#pragma unroll
            for (int p = 0; p < 8; p++) {
                const float ph = tanhf(red16[p][0] + pb[p]) * 3.14159265358979323846f;
                const float am = softplusf(red16[8 + p][0] + ab[p]) + 0.1f;
                c += am * (cosf(ph) + sinf(ph));
            }
            coef[t] = c;
        }
    }
}

/* ---------------- chunked cumulative sum over L ---------------- */
__global__ void chunk_sum_kernel(const float* __restrict__ val,
                                 float* __restrict__ csum) {
    const int c = blockIdx.x, b = blockIdx.y, d = threadIdx.x;
    const float* p = val + ((long)(b * Lm + c * CHL)) * Dm + d;
    float s = 0.f;
#pragma unroll 8
    for (int l = 0; l < CHL; l++) s += p[(long)l * Dm];
    csum[(b * NCH + c) * Dm + d] = s;
}

__global__ void chunk_scan_kernel(const float* __restrict__ val,
                                  const float* __restrict__ csum,
                                  float* __restrict__ ret) {
    const int c = blockIdx.x, b = blockIdx.y, d = threadIdx.x;
    float run = 0.f;
    for (int cc = 0; cc < c; cc++) run += csum[(b * NCH + cc) * Dm + d];
    const float* p = val + ((long)(b * Lm + c * CHL)) * Dm + d;
    float* q       = ret + ((long)(b * Lm + c * CHL)) * Dm + d;
    const float sc = 0.022097086912079608f;   /* 1/sqrt(2048) */
#pragma unroll 8
    for (int l = 0; l < CHL; l++) { run += p[(long)l * Dm]; q[(long)l * Dm] = run * sc; }
}

/* ---------------- fp32 SGEMM 128x128x8, 8x8 microtile, double-buffered ----
 * mode 0: C = A@B + bias
 * mode 1: C = (A@B + bias) * coef[m]
 * mode 2: C = A@B + bias + add1 + add2                                      */
__global__ void __launch_bounds__(256, 2) sgemm_kernel(
    const float* __restrict__ A, const float* __restrict__ B,
    float* __restrict__ C, int M, int N, int K,
    const float* __restrict__ bias, const float* __restrict__ coef,
    const float* __restrict__ add1, const float* __restrict__ add2, int mode)
{
    __shared__ float As[2][8][128];
    __shared__ float Bs[2][8][128];
    const int tid = threadIdx.x;
    const int tx = tid & 15;
    const int ty = tid >> 4;
    const int n0 = blockIdx.x * 128;
    const int m0 = blockIdx.y * 128;

    const int arow = tid >> 1;
    const int acol = (tid & 1) << 2;
    const int brow = tid >> 5;
    const int bcol = (tid & 31) << 2;

    const float* Ap = A + (long)(m0 + arow) * K + acol;
    const float* Bp = B + (long)brow * N + n0 + bcol;

    float acc[8][8];
#pragma unroll
    for (int i = 0; i < 8; i++)
#pragma unroll
        for (int j = 0; j < 8; j++) acc[i][j] = 0.f;

    float4 a4 = *(const float4*)Ap;
    float4 b4 = *(const float4*)Bp;
    As[0][acol + 0][arow] = a4.x; As[0][acol + 1][arow] = a4.y;
    As[0][acol + 2][arow] = a4.z; As[0][acol + 3][arow] = a4.w;
    *(float4*)&Bs[0][brow][bcol] = b4;
    __syncthreads();

    const int ktiles = K >> 3;
    for (int kt = 0; kt < ktiles; ++kt) {
        const int buf = kt & 1;
        float4 an, bn;
        const bool more = (kt + 1 < ktiles);
        if (more) {
            an = *(const float4*)(Ap + (kt + 1) * 8);
            bn = *(const float4*)(Bp + (long)(kt + 1) * 8 * N);
        }
#pragma unroll
        for (int k = 0; k < 8; k++) {
            float a[8], b[8];
            *(float4*)&a[0] = *(const float4*)&As[buf][k][ty * 4];
            *(float4*)&a[4] = *(const float4*)&As[buf][k][64 + ty * 4];
            *(float4*)&b[0] = *(const float4*)&Bs[buf][k][tx * 4];
            *(float4*)&b[4] = *(const float4*)&Bs[buf][k][64 + tx * 4];
#pragma unroll
            for (int i = 0; i < 8; i++)
#pragma unroll
                for (int j = 0; j < 8; j++) acc[i][j] += a[i] * b[j];
        }
        if (more) {
            const int nb = buf ^ 1;
            As[nb][acol + 0][arow] = an.x; As[nb][acol + 1][arow] = an.y;
            As[nb][acol + 2][arow] = an.z; As[nb][acol + 3][arow] = an.w;
            *(float4*)&Bs[nb][brow][bcol] = bn;
        }
        __syncthreads();
    }

#pragma unroll
    for (int i = 0; i < 8; i++) {
        const int mrow = m0 + ((i < 4) ? (ty * 4 + i) : (64 + ty * 4 + (i - 4)));
        const float cf = (mode == 1) ? coef[mrow] : 1.f;
#pragma unroll
        for (int jj = 0; jj < 2; jj++) {
            const int n = n0 + tx * 4 + jj * 64;
            float4 r;
            r.x = acc[i][jj * 4 + 0]; r.y = acc[i][jj * 4 + 1];
            r.z = acc[i][jj * 4 + 2]; r.w = acc[i][jj * 4 + 3];
            const float4 bb = *(const float4*)(bias + n);
            r.x += bb.x; r.y += bb.y; r.z += bb.z; r.w += bb.w;
            if (mode == 1) { r.x *= cf; r.y *= cf; r.z *= cf; r.w *= cf; }
            if (mode == 2) {
                const float4 h1 = *(const float4*)(add1 + (long)mrow * N + n);
                const float4 h2 = *(const float4*)(add2 + (long)mrow * N + n);
                r.x += h1.x + h2.x; r.y += h1.y + h2.y;
                r.z += h1.z + h2.z; r.w += h1.w + h2.w;
            }
            *(float4*)(C + (long)mrow * N + n) = r;
        }
    }
}

/* ---------------- driver ---------------- */
extern "C" void kernel_launch(void* const* d_in, const int* in_sizes, int n_in,
                              void* d_out, int out_size)
{
    (void)in_sizes; (void)n_in; (void)out_size;
    const int*   tokens = (const int*)  d_in[0];
    const float* embedw = (const float*)d_in[1];
    const float* ln_s   = (const float*)d_in[2];
    const float* ln_b   = (const float*)d_in[3];
    const float* pW     = (const float*)d_in[4];
    const float* pb     = (const float*)d_in[5];
    const float* aW     = (const float*)d_in[6];
    const float* ab     = (const float*)d_in[7];
    const float* vW     = (const float*)d_in[8];
    const float* vb     = (const float*)d_in[9];
    const float* oLNs   = (const float*)d_in[10];
    const float* oLNb   = (const float*)d_in[11];
    const float* oW     = (const float*)d_in[12];
    const float* ob     = (const float*)d_in[13];
    const float* nos    = (const float*)d_in[14];
    const float* nob    = (const float*)d_in[15];
    const float* hW     = (const float*)d_in[16];
    const float* hb     = (const float*)d_in[17];
    float* out = (float*)d_out;

    float *h, *hn, *rn, *val, *ret, *coef, *csum;
    cudaGetSymbolAddress((void**)&h,    g_h);
    cudaGetSymbolAddress((void**)&hn,   g_hn);
    cudaGetSymbolAddress((void**)&rn,   g_rn);
    cudaGetSymbolAddress((void**)&val,  g_val);
    cudaGetSymbolAddress((void**)&ret,  g_ret);
    cudaGetSymbolAddress((void**)&coef, g_coef);
    cudaGetSymbolAddress((void**)&csum, g_csum);

    embed_kernel<<<NT, 128>>>(tokens, embedw, h);

    for (int i = 0; i < NLAYER; i++) {
        ln_kernel<<<NT, 256>>>(h, hn, ln_s + i * Dm, ln_b + i * Dm,
                               pW + (long)i * Dm * Pm, pb + i * Pm,
                               aW + (long)i * Dm * Pm, ab + i * Pm, coef, 1);
        sgemm_kernel<<<dim3(Dm / 128, NT / 128), 256>>>(
            hn, vW + (long)i * Dm * Dm, val, NT, Dm, Dm,
            vb + i * Dm, coef, nullptr, nullptr, 1);
        chunk_sum_kernel<<<dim3(NCH, BATCH), Dm>>>(val, csum);
        chunk_scan_kernel<<<dim3(NCH, BATCH), Dm>>>(val, csum, ret);
        ln_kernel<<<NT, 256>>>(ret, rn, oLNs + i * Dm, oLNb + i * Dm,
                               nullptr, nullptr, nullptr, nullptr, nullptr, 0);
        sgemm_kernel<<<dim3(Dm / 128, NT / 128), 256>>>(
            rn, oW + (long)i * Dm * Dm, h, NT, Dm, Dm,
            ob + i * Dm, nullptr, h, hn, 2);
    }

    ln_kernel<<<NT, 256>>>(h, hn, nos, nob,
                           nullptr, nullptr, nullptr, nullptr, nullptr, 0);
    sgemm_kernel<<<dim3(Vm / 128, NT / 128), 256>>>(
        hn, hW, out, NT, Vm, Dm, hb, nullptr, nullptr, nullptr, 0);
}

// round 6
// speedup vs baseline: 1.8145x; 1.8145x over previous
#include <cuda_runtime.h>
#include <cuda_fp16.h>
#include <math.h>
#include <stdint.h>

#define Dm 512
#define Lm 2048
#define BATCH 2
#define NLAYER 4
#define Pm 8
#define Vm 32000
#define NT (BATCH*Lm)   /* 4096 tokens */
#define NCH 16
#define CHL (Lm/NCH)    /* 128 */

/* ---------------- scratch (no allocation allowed) ---------------- */
__device__ float g_h  [NT*Dm];
__device__ float g_hn [NT*Dm];
__device__ float g_rn [NT*Dm];
__device__ float g_val[NT*Dm];
__device__ float g_ret[NT*Dm];
__device__ float g_coef[NT];
__device__ float g_csum[BATCH*NCH*Dm];
__device__ __half g_ah[NT*Dm];       /* A hi */
__device__ __half g_al[NT*Dm];       /* A lo */
__device__ __half g_bh[(long)Vm*Dm]; /* B^T hi  [N,K] */
__device__ __half g_bl[(long)Vm*Dm]; /* B^T lo  [N,K] */

/* ---------------- PTX helpers (baseline ISA, valid on sm_103) ---------- */
__device__ __forceinline__ uint32_t smem_to_u32(const void* p) {
    uint32_t a;
    asm("{ .reg .u64 t; cvta.to.shared.u64 t, %1; cvt.u32.u64 %0, t; }" : "=r"(a) : "l"(p));
    return a;
}
#define CP_ASYNC16(dst, src) \
    asm volatile("cp.async.cg.shared.global [%0], [%1], 16;" :: "r"(dst), "l"(src))
#define CP_COMMIT() asm volatile("cp.async.commit_group;" ::: "memory")
#define CP_WAIT2()  asm volatile("cp.async.wait_group 2;" ::: "memory")
#define LDSM4(r0, r1, r2, r3, addr) \
    asm volatile("ldmatrix.sync.aligned.m8n8.x4.shared.b16 {%0,%1,%2,%3}, [%4];" \
                 : "=r"(r0), "=r"(r1), "=r"(r2), "=r"(r3) : "r"(addr))
#define MMA16816(d, a, b) \
    asm volatile("mma.sync.aligned.m16n8k16.row.col.f32.f16.f16.f32 " \
                 "{%0,%1,%2,%3}, {%4,%5,%6,%7}, {%8,%9}, {%0,%1,%2,%3};" \
                 : "+f"((d)[0]), "+f"((d)[1]), "+f"((d)[2]), "+f"((d)[3]) \
                 : "r"((a)[0]), "r"((a)[1]), "r"((a)[2]), "r"((a)[3]), \
                   "r"((b)[0]), "r"((b)[1]))

/* ---------------- helpers ---------------- */
__device__ __forceinline__ float warp_sum(float v) {
#pragma unroll
    for (int o = 16; o > 0; o >>= 1) v += __shfl_down_sync(0xffffffffu, v, o);
    return v;
}
__device__ __forceinline__ float softplusf(float x) {
    return (x > 20.f) ? x : log1pf(expf(x));
}

/* ---------------- embedding gather ---------------- */
__global__ void embed_kernel(const int* __restrict__ tok,
                             const float* __restrict__ emb,
                             float* __restrict__ h) {
    const int t = blockIdx.x;
    const int tk = tok[t];
    const float4* s = (const float4*)(emb + (long)tk * Dm);
    float4* d = (float4*)(h + (long)t * Dm);
    d[threadIdx.x] = s[threadIdx.x];
}

/* ---------------- LayerNorm (+ optional fused phase/amp coef) ---------- */
__global__ void __launch_bounds__(256) ln_kernel(
    const float* __restrict__ X, float* __restrict__ Y,
    const float* __restrict__ gamma, const float* __restrict__ beta,
    const float* __restrict__ pW, const float* __restrict__ pb,
    const float* __restrict__ aW, const float* __restrict__ ab,
    float* __restrict__ coef, int docoef)
{
    const int t = blockIdx.x;
    const int tid = threadIdx.x;
    const int w = tid >> 5, lane = tid & 31;

    const float2 v = ((const float2*)(X + (long)t * Dm))[tid];
    float s  = v.x + v.y;
    float ss = v.x * v.x + v.y * v.y;

    __shared__ float sred[2][8];
    __shared__ float smean, sinv;
    float ws = warp_sum(s), wss = warp_sum(ss);
    if (lane == 0) { sred[0][w] = ws; sred[1][w] = wss; }
    __syncthreads();
    if (tid == 0) {
        float S = 0.f, SS = 0.f;
#pragma unroll
        for (int i = 0; i < 8; i++) { S += sred[0][i]; SS += sred[1][i]; }
        const float m = S * (1.f / Dm);
        const float var = SS * (1.f / Dm) - m * m;
        smean = m; sinv = rsqrtf(var + 1e-5f);
    }
    __syncthreads();
    const float m = smean, inv = sinv;
    const int d0 = tid * 2;
    const float y0 = (v.x - m) * inv * gamma[d0]     + beta[d0];
    const float y1 = (v.y - m) * inv * gamma[d0 + 1] + beta[d0 + 1];
    ((float2*)(Y + (long)t * Dm))[tid] = make_float2(y0, y1);

    if (docoef) {
        float pa[8], aa[8];
#pragma unroll
        for (int j = 0; j < 8; j++) { pa[j] = 0.f; aa[j] = 0.f; }
        const float4* pw4 = (const float4*)(pW + (long)d0 * Pm);
        const float4* aw4 = (const float4*)(aW + (long)d0 * Pm);
        const float ys[2] = { y0, y1 };
#pragma unroll
        for (int dd = 0; dd < 2; dd++) {
            const float yv = ys[dd];
            float4 w0 = pw4[dd * 2], w1 = pw4[dd * 2 + 1];
            pa[0] += yv * w0.x; pa[1] += yv * w0.y; pa[2] += yv * w0.z; pa[3] += yv * w0.w;
            pa[4] += yv * w1.x; pa[5] += yv * w1.y; pa[6] += yv * w1.z; pa[7] += yv * w1.w;
            w0 = aw4[dd * 2]; w1 = aw4[dd * 2 + 1];
            aa[0] += yv * w0.x; aa[1] += yv * w0.y; aa[2] += yv * w0.z; aa[3] += yv * w0.w;
            aa[4] += yv * w1.x; aa[5] += yv * w1.y; aa[6] += yv * w1.z; aa[7] += yv * w1.w;
        }
        __shared__ float red16[16][8];
#pragma unroll
        for (int j = 0; j < 8; j++) {
            float r = warp_sum(pa[j]); if (lane == 0) red16[j][w] = r;
            r = warp_sum(aa[j]);       if (lane == 0) red16[8 + j][w] = r;
        }
        __syncthreads();
        if (tid < 16) {
            float r = 0.f;
#pragma unroll
            for (int i = 0; i < 8; i++) r += red16[tid][i];
            red16[tid][0] = r;
        }
        __syncthreads();
        if (tid == 0) {
            float c = 0.f;
#pragma unroll
            for (int p = 0; p < 8; p++) {
                const float ph = tanhf(red16[p][0] + pb[p]) * 3.14159265358979323846f;
                const float am = softplusf(red16[8 + p][0] + ab[p]) + 0.1f;
                c += am * (cosf(ph) + sinf(ph));
            }
            coef[t] = c;
        }
    }
}

/* ---------------- chunked cumulative sum over L ---------------- */
__global__ void chunk_sum_kernel(const float* __restrict__ val,
                                 float* __restrict__ csum) {
    const int c = blockIdx.x, b = blockIdx.y, d = threadIdx.x;
    const float* p = val + ((long)(b * Lm + c * CHL)) * Dm + d;
    float s = 0.f;
#pragma unroll 8
    for (int l = 0; l < CHL; l++) s += p[(long)l * Dm];
    csum[(b * NCH + c) * Dm + d] = s;
}

__global__ void chunk_scan_kernel(const float* __restrict__ val,
                                  const float* __restrict__ csum,
                                  float* __restrict__ ret) {
    const int c = blockIdx.x, b = blockIdx.y, d = threadIdx.x;
    float run = 0.f;
    for (int cc = 0; cc < c; cc++) run += csum[(b * NCH + cc) * Dm + d];
    const float* p = val + ((long)(b * Lm + c * CHL)) * Dm + d;
    float* q       = ret + ((long)(b * Lm + c * CHL)) * Dm + d;
    const float sc = 0.022097086912079608f;   /* 1/sqrt(2048) */
#pragma unroll 8
    for (int l = 0; l < CHL; l++) { run += p[(long)l * Dm]; q[(long)l * Dm] = run * sc; }
}

/* ---------------- fp16 hi/lo split (elementwise, A matrices) ----------- */
__global__ void __launch_bounds__(256) split_kernel(
    const float* __restrict__ X,
    __half* __restrict__ H, __half* __restrict__ L)
{
    const long i = ((long)blockIdx.x * 256 + threadIdx.x) * 4;
    const float4 v = *(const float4*)(X + i);
    __half h0 = __float2half_rn(v.x);
    __half h1 = __float2half_rn(v.y);
    __half h2 = __float2half_rn(v.z);
    __half h3 = __float2half_rn(v.w);
    __half l0 = __float2half_rn(v.x - __half2float(h0));
    __half l1 = __float2half_rn(v.y - __half2float(h1));
    __half l2 = __float2half_rn(v.z - __half2float(h2));
    __half l3 = __float2half_rn(v.w - __half2float(h3));
    __half2* Hp = (__half2*)(H + i);
    __half2* Lp = (__half2*)(L + i);
    Hp[0] = __halves2half2(h0, h1); Hp[1] = __halves2half2(h2, h3);
    Lp[0] = __halves2half2(l0, l1); Lp[1] = __halves2half2(l2, l3);
}

/* ---------------- transpose + split: W[K,N] fp32 -> Bt[N,K] fp16 hi/lo - */
__global__ void __launch_bounds__(256) tsplit_kernel(
    const float* __restrict__ W,
    __half* __restrict__ Bh, __half* __restrict__ Bl,
    int K, int N)
{
    __shared__ float tile[32][33];
    const int n0 = blockIdx.x * 32, k0 = blockIdx.y * 32;
    const int c = threadIdx.x & 31, r0 = threadIdx.x >> 5;
#pragma unroll
    for (int i = 0; i < 4; i++) {
        const int r = r0 + i * 8;
        tile[r][c] = W[(long)(k0 + r) * N + n0 + c];
    }
    __syncthreads();
#pragma unroll
    for (int i = 0; i < 4; i++) {
        const int r = r0 + i * 8;            /* n index within tile */
        const float v = tile[c][r];
        const __half h = __float2half_rn(v);
        const __half l = __float2half_rn(v - __half2float(h));
        const long o = (long)(n0 + r) * K + k0 + c;
        Bh[o] = h; Bl[o] = l;
    }
}

/* ---------------- warp-MMA GEMM: C[M,N] = A[M,K] @ Bt[N,K]^T ------------
 * fp16 split: C = Ah*Bh + Al*Bh (+ Ah*Bl when use_bl).
 * 128x128 CTA tile, 8 warps of 64x32, K-tile 32, 3-stage cp.async.
 * SMEM row pitch 80 B (64 data + 16 pad) -> conflict-free ldmatrix.
 * mode 0: +bias; 1: (x+bias)*coef[m]; 2: +bias+add1+add2                 */
#define ARR_STRIDE 10240                 /* 128 rows x 80B */
#define STG_STRIDE (4*ARR_STRIDE)        /* Ah | Al | Bh | Bl */
#define GEMM_SMEM  (3*STG_STRIDE)        /* 3 stages = 122880B */

__global__ void __launch_bounds__(256) hm_gemm_kernel(
    const __half* __restrict__ Ah, const __half* __restrict__ Al,
    const __half* __restrict__ Bh, const __half* __restrict__ Bl,
    float* __restrict__ C, int M, int N, int K,
    const float* __restrict__ bias, const float* __restrict__ coef,
    const float* __restrict__ add1, const float* __restrict__ add2,
    int mode, int use_bl)
{
    extern __shared__ char smem[];
    const uint32_t sbase = smem_to_u32(smem);
    const int tid = threadIdx.x;
    const int wid = tid >> 5, lane = tid & 31;
    const int n0 = blockIdx.x * 128, m0 = blockIdx.y * 128;
    const int wm = (wid >> 2) * 64;       /* warp m offset in tile */
    const int wn = (wid & 3) * 32;        /* warp n offset in tile */
    const int narr = use_bl ? 4 : 3;
    const int nkt = K >> 5;               /* K-tiles of 32 */

    const __half* srcs[4] = { Ah, Al, Bh, Bl };

    float acc[4][4][4];
#pragma unroll
    for (int i = 0; i < 4; i++)
#pragma unroll
        for (int j = 0; j < 4; j++)
#pragma unroll
            for (int q = 0; q < 4; q++) acc[i][j][q] = 0.f;

    /* ---- async stage loader: 128 rows x 4 x 16B per array ---- */
    auto load_stage = [&](int buf, int kt) {
        const int kbase = kt * 32;
        const uint32_t dstb = sbase + (uint32_t)buf * STG_STRIDE;
        for (int arr = 0; arr < narr; arr++) {
            const __half* src = srcs[arr];
            const int rbase = (arr < 2) ? m0 : n0;
            const uint32_t d0 = dstb + (uint32_t)arr * ARR_STRIDE;
#pragma unroll
            for (int i = 0; i < 2; i++) {
                const int idx = i * 256 + tid;     /* 0..511 */
                const int row = idx >> 2, c = idx & 3;
                CP_ASYNC16(d0 + row * 80 + c * 16,
                           src + (long)(rbase + row) * K + kbase + c * 8);
            }
        }
    };

    load_stage(0, 0); CP_COMMIT();
    load_stage(1, 1); CP_COMMIT();

    const int mat = lane >> 3, mr = lane & 7;

    for (int kt = 0; kt < nkt; kt++) {
        if (kt + 2 < nkt) load_stage((kt + 2) % 3, kt + 2);
        CP_COMMIT();
        CP_WAIT2();
        __syncthreads();

        const uint32_t base = sbase + (uint32_t)(kt % 3) * STG_STRIDE;
#pragma unroll
        for (int kk = 0; kk < 2; kk++) {
            uint32_t ahf[4][4], alf[4][4], bhf[4][2], blf[4][2];
            /* B fragments: mat -> (n_off = (mat>>1)*8, k_off = (mat&1)*16B) */
#pragma unroll
            for (int pr = 0; pr < 2; pr++) {
                const uint32_t baddr = base + 2 * ARR_STRIDE
                    + (uint32_t)(wn + pr * 16 + ((mat >> 1) << 3) + mr) * 80
                    + kk * 32 + ((mat & 1) << 4);
                LDSM4(bhf[pr*2][0], bhf[pr*2][1], bhf[pr*2+1][0], bhf[pr*2+1][1], baddr);
                if (use_bl) {
                    LDSM4(blf[pr*2][0], blf[pr*2][1], blf[pr*2+1][0], blf[pr*2+1][1],
                          baddr + ARR_STRIDE);
                }
            }
            /* A fragments: mat -> (m_off = (mat&1)*8, k_off = (mat>>1)*16B) */
#pragma unroll
            for (int mt = 0; mt < 4; mt++) {
                const uint32_t aoff =
                    (uint32_t)(wm + mt * 16 + ((mat & 1) << 3) + mr) * 80
                    + kk * 32 + ((mat >> 1) << 4);
                LDSM4(ahf[mt][0], ahf[mt][1], ahf[mt][2], ahf[mt][3], base + aoff);
                LDSM4(alf[mt][0], alf[mt][1], alf[mt][2], alf[mt][3],
                      base + ARR_STRIDE + aoff);
            }
#pragma unroll
            for (int mt = 0; mt < 4; mt++)
#pragma unroll
                for (int nt = 0; nt < 4; nt++) {
                    MMA16816(acc[mt][nt], ahf[mt], bhf[nt]);
                    MMA16816(acc[mt][nt], alf[mt], bhf[nt]);
                    if (use_bl) MMA16816(acc[mt][nt], ahf[mt], blf[nt]);
                }
        }
        __syncthreads();
    }

    /* ---- epilogue: fragment (r = lane/4 & +8, c = (lane%4)*2) ---- */
    const int qr = lane >> 2, qc = (lane & 3) * 2;
#pragma unroll
    for (int mt = 0; mt < 4; mt++) {
        const int r0 = m0 + wm + mt * 16 + qr;
        const int r1 = r0 + 8;
        const float cf0 = (mode == 1) ? coef[r0] : 1.f;
        const float cf1 = (mode == 1) ? coef[r1] : 1.f;
#pragma unroll
        for (int nt = 0; nt < 4; nt++) {
            const int col = n0 + wn + nt * 8 + qc;
            const float2 bb = *(const float2*)(bias + col);
            float2 v0, v1;
            v0.x = acc[mt][nt][0] + bb.x; v0.y = acc[mt][nt][1] + bb.y;
            v1.x = acc[mt][nt][2] + bb.x; v1.y = acc[mt][nt][3] + bb.y;
            if (mode == 1) { v0.x *= cf0; v0.y *= cf0; v1.x *= cf1; v1.y *= cf1; }
            if (mode == 2) {
                const float2 a10 = *(const float2*)(add1 + (long)r0 * N + col);
                const float2 a11 = *(const float2*)(add1 + (long)r1 * N + col);
                const float2 a20 = *(const float2*)(add2 + (long)r0 * N + col);
                const float2 a21 = *(const float2*)(add2 + (long)r1 * N + col);
                v0.x += a10.x + a20.x; v0.y += a10.y + a20.y;
                v1.x += a11.x + a21.x; v1.y += a11.y + a21.y;
            }
            *(float2*)(C + (long)r0 * N + col) = v0;
            *(float2*)(C + (long)r1 * N + col) = v1;
        }
    }
}

/* ---------------- driver ---------------- */
extern "C" void kernel_launch(void* const* d_in, const int* in_sizes, int n_in,
                              void* d_out, int out_size)
{
    (void)in_sizes; (void)n_in; (void)out_size;
    const int*   tokens = (const int*)  d_in[0];
    const float* embedw = (const float*)d_in[1];
    const float* ln_s   = (const float*)d_in[2];
    const float* ln_b   = (const float*)d_in[3];
    const float* pW     = (const float*)d_in[4];
    const float* pb     = (const float*)d_in[5];
    const float* aW     = (const float*)d_in[6];
    const float* ab     = (const float*)d_in[7];
    const float* vW     = (const float*)d_in[8];
    const float* vb     = (const float*)d_in[9];
    const float* oLNs   = (const float*)d_in[10];
    const float* oLNb   = (const float*)d_in[11];
    const float* oW     = (const float*)d_in[12];
    const float* ob     = (const float*)d_in[13];
    const float* nos    = (const float*)d_in[14];
    const float* nob    = (const float*)d_in[15];
    const float* hW     = (const float*)d_in[16];
    const float* hb     = (const float*)d_in[17];
    float* out = (float*)d_out;

    float *h, *hn, *rn, *val, *ret, *coef, *csum;
    __half *ah, *al, *bh, *bl;
    cudaGetSymbolAddress((void**)&h,    g_h);
    cudaGetSymbolAddress((void**)&hn,   g_hn);
    cudaGetSymbolAddress((void**)&rn,   g_rn);
    cudaGetSymbolAddress((void**)&val,  g_val);
    cudaGetSymbolAddress((void**)&ret,  g_ret);
    cudaGetSymbolAddress((void**)&coef, g_coef);
    cudaGetSymbolAddress((void**)&csum, g_csum);
    cudaGetSymbolAddress((void**)&ah,   g_ah);
    cudaGetSymbolAddress((void**)&al,   g_al);
    cudaGetSymbolAddress((void**)&bh,   g_bh);
    cudaGetSymbolAddress((void**)&bl,   g_bl);

    cudaFuncSetAttribute(hm_gemm_kernel,
                         cudaFuncAttributeMaxDynamicSharedMemorySize, GEMM_SMEM);

    const int splitBlocks = (NT * Dm) / (256 * 4);

    embed_kernel<<<NT, 128>>>(tokens, embedw, h);

    for (int i = 0; i < NLAYER; i++) {
        ln_kernel<<<NT, 256>>>(h, hn, ln_s + i * Dm, ln_b + i * Dm,
                               pW + (long)i * Dm * Pm, pb + i * Pm,
                               aW + (long)i * Dm * Pm, ab + i * Pm, coef, 1);
        split_kernel<<<splitBlocks, 256>>>(hn, ah, al);
        tsplit_kernel<<<dim3(Dm / 32, Dm / 32), 256>>>(vW + (long)i * Dm * Dm, bh, bl, Dm, Dm);
        hm_gemm_kernel<<<dim3(Dm / 128, NT / 128), 256, GEMM_SMEM>>>(
            ah, al, bh, bl, val, NT, Dm, Dm,
            vb + i * Dm, coef, nullptr, nullptr, 1, 1);
        chunk_sum_kernel<<<dim3(NCH, BATCH), Dm>>>(val, csum);
        chunk_scan_kernel<<<dim3(NCH, BATCH), Dm>>>(val, csum, ret);
        ln_kernel<<<NT, 256>>>(ret, rn, oLNs + i * Dm, oLNb + i * Dm,
                               nullptr, nullptr, nullptr, nullptr, nullptr, 0);
        split_kernel<<<splitBlocks, 256>>>(rn, ah, al);
        tsplit_kernel<<<dim3(Dm / 32, Dm / 32), 256>>>(oW + (long)i * Dm * Dm, bh, bl, Dm, Dm);
        hm_gemm_kernel<<<dim3(Dm / 128, NT / 128), 256, GEMM_SMEM>>>(
            ah, al, bh, bl, h, NT, Dm, Dm,
            ob + i * Dm, nullptr, h, hn, 2, 1);
    }

    ln_kernel<<<NT, 256>>>(h, hn, nos, nob,
                           nullptr, nullptr, nullptr, nullptr, nullptr, 0);
    split_kernel<<<splitBlocks, 256>>>(hn, ah, al);
    tsplit_kernel<<<dim3(Vm / 32, Dm / 32), 256>>>(hW, bh, bl, Dm, Vm);
    hm_gemm_kernel<<<dim3(Vm / 128, NT / 128), 256, GEMM_SMEM>>>(
        ah, al, bh, bl, out, NT, Vm, Dm,
        hb, nullptr, nullptr, nullptr, 0, 0);
}

// round 10
// speedup vs baseline: 3.1495x; 1.7358x over previous
#include <cuda_runtime.h>
#include <cuda_fp16.h>
#include <math.h>
#include <stdint.h>

#define Dm 512
#define Lm 2048
#define BATCH 2
#define NLAYER 4
#define Pm 8
#define Vm 32000
#define NT (BATCH*Lm)   /* 4096 tokens */
#define NCH 64
#define CHL (Lm/NCH)    /* 32 */

/* ---------------- scratch (no allocation allowed) ---------------- */
__device__ float g_h  [NT*Dm];
__device__ float g_hn [NT*Dm];
__device__ float g_rn [NT*Dm];
__device__ float g_val[NT*Dm];
__device__ float g_ret[NT*Dm];
__device__ float g_coef[NT];
__device__ float g_csum[BATCH*NCH*Dm];
__device__ __half g_ah[NT*Dm];       /* A hi */
__device__ __half g_al[NT*Dm];       /* A lo */
__device__ __half g_bh[(long)Vm*Dm]; /* B^T hi  [N,K] */
__device__ __half g_bl[(long)Vm*Dm]; /* B^T lo  [N,K] */

/* ---------------- PTX helpers (baseline ISA, valid on sm_103) ---------- */
__device__ __forceinline__ uint32_t smem_to_u32(const void* p) {
    uint32_t a;
    asm("{ .reg .u64 t; cvta.to.shared.u64 t, %1; cvt.u32.u64 %0, t; }" : "=r"(a) : "l"(p));
    return a;
}
#define CP_ASYNC16(dst, src) \
    asm volatile("cp.async.cg.shared.global [%0], [%1], 16;" :: "r"(dst), "l"(src))
#define CP_COMMIT() asm volatile("cp.async.commit_group;" ::: "memory")
#define CP_WAIT2()  asm volatile("cp.async.wait_group 2;" ::: "memory")
#define LDSM4(r0, r1, r2, r3, addr) \
    asm volatile("ldmatrix.sync.aligned.m8n8.x4.shared.b16 {%0,%1,%2,%3}, [%4];" \
                 : "=r"(r0), "=r"(r1), "=r"(r2), "=r"(r3) : "r"(addr))
#define MMA16816(d, a, b) \
    asm volatile("mma.sync.aligned.m16n8k16.row.col.f32.f16.f16.f32 " \
                 "{%0,%1,%2,%3}, {%4,%5,%6,%7}, {%8,%9}, {%0,%1,%2,%3};" \
                 : "+f"((d)[0]), "+f"((d)[1]), "+f"((d)[2]), "+f"((d)[3]) \
                 : "r"((a)[0]), "r"((a)[1]), "r"((a)[2]), "r"((a)[3]), \
                   "r"((b)[0]), "r"((b)[1]))

/* ---------------- helpers ---------------- */
__device__ __forceinline__ float warp_sum(float v) {
#pragma unroll
    for (int o = 16; o > 0; o >>= 1) v += __shfl_down_sync(0xffffffffu, v, o);
    return v;
}
__device__ __forceinline__ float softplusf(float x) {
    return (x > 20.f) ? x : log1pf(expf(x));
}

/* ---------------- embedding gather ---------------- */
__global__ void embed_kernel(const int* __restrict__ tok,
                             const float* __restrict__ emb,
                             float* __restrict__ h) {
    const int t = blockIdx.x;
    const int tk = tok[t];
    const float4* s = (const float4*)(emb + (long)tk * Dm);
    float4* d = (float4*)(h + (long)t * Dm);
    d[threadIdx.x] = s[threadIdx.x];
}

/* ---------------- LayerNorm (+ optional fused phase/amp coef) ---------- */
__global__ void __launch_bounds__(256) ln_kernel(
    const float* __restrict__ X, float* __restrict__ Y,
    const float* __restrict__ gamma, const float* __restrict__ beta,
    const float* __restrict__ pW, const float* __restrict__ pb,
    const float* __restrict__ aW, const float* __restrict__ ab,
    float* __restrict__ coef, int docoef)
{
    const int t = blockIdx.x;
    const int tid = threadIdx.x;
    const int w = tid >> 5, lane = tid & 31;

    const float2 v = ((const float2*)(X + (long)t * Dm))[tid];
    float s  = v.x + v.y;
    float ss = v.x * v.x + v.y * v.y;

    __shared__ float sred[2][8];
    __shared__ float smean, sinv;
    float ws = warp_sum(s), wss = warp_sum(ss);
    if (lane == 0) { sred[0][w] = ws; sred[1][w] = wss; }
    __syncthreads();
    if (tid == 0) {
        float S = 0.f, SS = 0.f;
#pragma unroll
        for (int i = 0; i < 8; i++) { S += sred[0][i]; SS += sred[1][i]; }
        const float m = S * (1.f / Dm);
        const float var = SS * (1.f / Dm) - m * m;
        smean = m; sinv = rsqrtf(var + 1e-5f);
    }
    __syncthreads();
    const float m = smean, inv = sinv;
    const int d0 = tid * 2;
    const float y0 = (v.x - m) * inv * gamma[d0]     + beta[d0];
    const float y1 = (v.y - m) * inv * gamma[d0 + 1] + beta[d0 + 1];
    ((float2*)(Y + (long)t * Dm))[tid] = make_float2(y0, y1);

    if (docoef) {
        float pa[8], aa[8];
#pragma unroll
        for (int j = 0; j < 8; j++) { pa[j] = 0.f; aa[j] = 0.f; }
        const float4* pw4 = (const float4*)(pW + (long)d0 * Pm);
        const float4* aw4 = (const float4*)(aW + (long)d0 * Pm);
        const float ys[2] = { y0, y1 };
#pragma unroll
        for (int dd = 0; dd < 2; dd++) {
            const float yv = ys[dd];
            float4 w0 = pw4[dd * 2], w1 = pw4[dd * 2 + 1];
            pa[0] += yv * w0.x; pa[1] += yv * w0.y; pa[2] += yv * w0.z; pa[3] += yv * w0.w;
            pa[4] += yv * w1.x; pa[5] += yv * w1.y; pa[6] += yv * w1.z; pa[7] += yv * w1.w;
            w0 = aw4[dd * 2]; w1 = aw4[dd * 2 + 1];
            aa[0] += yv * w0.x; aa[1] += yv * w0.y; aa[2] += yv * w0.z; aa[3] += yv * w0.w;
            aa[4] += yv * w1.x; aa[5] += yv * w1.y; aa[6] += yv * w1.z; aa[7] += yv * w1.w;
        }
        __shared__ float red16[16][8];
#pragma unroll
        for (int j = 0; j < 8; j++) {
            float r = warp_sum(pa[j]); if (lane == 0) red16[j][w] = r;
            r = warp_sum(aa[j]);       if (lane == 0) red16[8 + j][w] = r;
        }
        __syncthreads();
        if (tid < 16) {
            float r = 0.f;
#pragma unroll
            for (int i = 0; i < 8; i++) r += red16[tid][i];
            red16[tid][0] = r;
        }
        __syncthreads();
        if (tid == 0) {
            float c = 0.f;
#pragma unroll
            for (int p = 0; p < 8; p++) {
                const float ph = tanhf(red16[p][0] + pb[p]) * 3.14159265358979323846f;
                const float am = softplusf(red16[8 + p][0] + ab[p]) + 0.1f;
                c += am * (cosf(ph) + sinf(ph));
            }
            coef[t] = c;
        }
    }
}

/* ---------------- chunked cumulative sum over L ---------------- */
__global__ void chunk_sum_kernel(const float* __restrict__ val,
                                 float* __restrict__ csum) {
    const int c = blockIdx.x, b = blockIdx.y, d = threadIdx.x;
    const float* p = val + ((long)(b * Lm + c * CHL)) * Dm + d;
    float s = 0.f;
#pragma unroll 8
    for (int l = 0; l < CHL; l++) s += p[(long)l * Dm];
    csum[(b * NCH + c) * Dm + d] = s;
}

__global__ void chunk_scan_kernel(const float* __restrict__ val,
                                  const float* __restrict__ csum,
                                  float* __restrict__ ret) {
    const int c = blockIdx.x, b = blockIdx.y, d = threadIdx.x;
    float run = 0.f;
    for (int cc = 0; cc < c; cc++) run += csum[(b * NCH + cc) * Dm + d];
    const float* p = val + ((long)(b * Lm + c * CHL)) * Dm + d;
    float* q       = ret + ((long)(b * Lm + c * CHL)) * Dm + d;
    const float sc = 0.022097086912079608f;   /* 1/sqrt(2048) */
#pragma unroll 8
    for (int l = 0; l < CHL; l++) { run += p[(long)l * Dm]; q[(long)l * Dm] = run * sc; }
}

/* ---------------- fp16 hi/lo split (elementwise, A matrices) ----------- */
__global__ void __launch_bounds__(256) split_kernel(
    const float* __restrict__ X,
    __half* __restrict__ H, __half* __restrict__ L)
{
    const long i = ((long)blockIdx.x * 256 + threadIdx.x) * 4;
    const float4 v = *(const float4*)(X + i);
    __half h0 = __float2half_rn(v.x);
    __half h1 = __float2half_rn(v.y);
    __half h2 = __float2half_rn(v.z);
    __half h3 = __float2half_rn(v.w);
    __half l0 = __float2half_rn(v.x - __half2float(h0));
    __half l1 = __float2half_rn(v.y - __half2float(h1));
    __half l2 = __float2half_rn(v.z - __half2float(h2));
    __half l3 = __float2half_rn(v.w - __half2float(h3));
    __half2* Hp = (__half2*)(H + i);
    __half2* Lp = (__half2*)(L + i);
    Hp[0] = __halves2half2(h0, h1); Hp[1] = __halves2half2(h2, h3);
    Lp[0] = __halves2half2(l0, l1); Lp[1] = __halves2half2(l2, l3);
}

/* ---------------- transpose + split: W[K,N] fp32 -> Bt[N,K] fp16 hi/lo - */
__global__ void __launch_bounds__(256) tsplit_kernel(
    const float* __restrict__ W,
    __half* __restrict__ Bh, __half* __restrict__ Bl,
    int K, int N, int wantlo)
{
    __shared__ float tile[32][33];
    const int n0 = blockIdx.x * 32, k0 = blockIdx.y * 32;
    const int c = threadIdx.x & 31, r0 = threadIdx.x >> 5;
#pragma unroll
    for (int i = 0; i < 4; i++) {
        const int r = r0 + i * 8;
        tile[r][c] = W[(long)(k0 + r) * N + n0 + c];
    }
    __syncthreads();
#pragma unroll
    for (int i = 0; i < 4; i++) {
        const int r = r0 + i * 8;            /* n index within tile */
        const float v = tile[c][r];
        const __half h = __float2half_rn(v);
        const long o = (long)(n0 + r) * K + k0 + c;
        Bh[o] = h;
        if (wantlo) Bl[o] = __float2half_rn(v - __half2float(h));
    }
}

/* ---------------- warp-MMA GEMM: C[M,N] = A[M,K] @ Bt[N,K]^T ------------
 * NPASS==3: C = Ah*Bh + Al*Bh + Ah*Bl  (arrays Ah|Al|Bh|Bl)
 * NPASS==1: C = Ah*Bh                  (arrays Ah|Bh, 3 CTAs/SM)
 * 128x128 CTA tile, 8 warps of 64x32, K-tile 32, 3-stage cp.async.
 * SMEM row pitch 80 B (64 data + 16 pad) -> conflict-free ldmatrix.
 * mode 0: +bias; 1: (x+bias)*coef[m]; 2: +bias+add1+add2                 */
#define ARR_STRIDE 10240u                /* 128 rows x 80B */

template<int NPASS>
__global__ void __launch_bounds__(256) hm_gemm_kernel(
    const __half* __restrict__ Ah, const __half* __restrict__ Al,
    const __half* __restrict__ Bh, const __half* __restrict__ Bl,
    float* __restrict__ C, int M, int N, int K,
    const float* __restrict__ bias, const float* __restrict__ coef,
    const float* __restrict__ add1, const float* __restrict__ add2,
    int mode)
{
    constexpr int NARR = (NPASS == 3) ? 4 : 2;
    constexpr uint32_t STG = NARR * ARR_STRIDE;
    constexpr uint32_t BHOFF = (NPASS == 3) ? 2 * ARR_STRIDE : ARR_STRIDE;

    extern __shared__ char smem[];
    const uint32_t sbase = smem_to_u32(smem);
    const int tid = threadIdx.x;
    const int wid = tid >> 5, lane = tid & 31;
    const int n0 = blockIdx.x * 128, m0 = blockIdx.y * 128;
    const int wm = (wid >> 2) * 64;       /* warp m offset in tile */
    const int wn = (wid & 3) * 32;        /* warp n offset in tile */
    const int nkt = K >> 5;               /* K-tiles of 32 */

    const __half* srcs[4];
    int rbase[4];
    if (NPASS == 3) {
        srcs[0] = Ah; srcs[1] = Al; srcs[2] = Bh; srcs[3] = Bl;
        rbase[0] = m0; rbase[1] = m0; rbase[2] = n0; rbase[3] = n0;
    } else {
        srcs[0] = Ah; srcs[1] = Bh;
        rbase[0] = m0; rbase[1] = n0;
    }

    float acc[4][4][4];
#pragma unroll
    for (int i = 0; i < 4; i++)
#pragma unroll
        for (int j = 0; j < 4; j++)
#pragma unroll
            for (int q = 0; q < 4; q++) acc[i][j][q] = 0.f;

    /* ---- async stage loader: 128 rows x 4 x 16B per array ---- */
    auto load_stage = [&](int buf, int kt) {
        const int kbase = kt * 32;
        const uint32_t dstb = sbase + (uint32_t)buf * STG;
#pragma unroll
        for (int arr = 0; arr < NARR; arr++) {
            const __half* src = srcs[arr];
            const uint32_t d0 = dstb + (uint32_t)arr * ARR_STRIDE;
#pragma unroll
            for (int i = 0; i < 2; i++) {
                const int idx = i * 256 + tid;     /* 0..511 */
                const int row = idx >> 2, c = idx & 3;
                CP_ASYNC16(d0 + row * 80 + c * 16,
                           src + (long)(rbase[arr] + row) * K + kbase + c * 8);
            }
        }
    };

    load_stage(0, 0); CP_COMMIT();
    load_stage(1, 1); CP_COMMIT();

    const int mat = lane >> 3, mr = lane & 7;

    for (int kt = 0; kt < nkt; kt++) {
        if (kt + 2 < nkt) load_stage((kt + 2) % 3, kt + 2);
        CP_COMMIT();
        CP_WAIT2();
        __syncthreads();

        const uint32_t base = sbase + (uint32_t)(kt % 3) * STG;
#pragma unroll
        for (int kk = 0; kk < 2; kk++) {
            uint32_t ahf[4][4], alf[4][4], bhf[4][2], blf[4][2];
            /* B fragments: mat -> (n_off = (mat>>1)*8, k_off = (mat&1)*16B) */
#pragma unroll
            for (int pr = 0; pr < 2; pr++) {
                const uint32_t baddr = base + BHOFF
                    + (uint32_t)(wn + pr * 16 + ((mat >> 1) << 3) + mr) * 80
                    + kk * 32 + ((mat & 1) << 4);
                LDSM4(bhf[pr*2][0], bhf[pr*2][1], bhf[pr*2+1][0], bhf[pr*2+1][1], baddr);
                if (NPASS == 3) {
                    LDSM4(blf[pr*2][0], blf[pr*2][1], blf[pr*2+1][0], blf[pr*2+1][1],
                          baddr + ARR_STRIDE);
                }
            }
            /* A fragments: mat -> (m_off = (mat&1)*8, k_off = (mat>>1)*16B) */
#pragma unroll
            for (int mt = 0; mt < 4; mt++) {
                const uint32_t aoff =
                    (uint32_t)(wm + mt * 16 + ((mat & 1) << 3) + mr) * 80
                    + kk * 32 + ((mat >> 1) << 4);
                LDSM4(ahf[mt][0], ahf[mt][1], ahf[mt][2], ahf[mt][3], base + aoff);
                if (NPASS == 3) {
                    LDSM4(alf[mt][0], alf[mt][1], alf[mt][2], alf[mt][3],
                          base + ARR_STRIDE + aoff);
                }
            }
#pragma unroll
            for (int mt = 0; mt < 4; mt++)
#pragma unroll
                for (int nt = 0; nt < 4; nt++) {
                    MMA16816(acc[mt][nt], ahf[mt], bhf[nt]);
                    if (NPASS == 3) {
                        MMA16816(acc[mt][nt], alf[mt], bhf[nt]);
                        MMA16816(acc[mt][nt], ahf[mt], blf[nt]);
                    }
                }
        }
        __syncthreads();
    }

    /* ---- epilogue: fragment (r = lane/4 & +8, c = (lane%4)*2) ---- */
    const int qr = lane >> 2, qc = (lane & 3) * 2;
#pragma unroll
    for (int mt = 0; mt < 4; mt++) {
        const int r0 = m0 + wm + mt * 16 + qr;
        const int r1 = r0 + 8;
        const float cf0 = (mode == 1) ? coef[r0] : 1.f;
        const float cf1 = (mode == 1) ? coef[r1] : 1.f;
#pragma unroll
        for (int nt = 0; nt < 4; nt++) {
            const int col = n0 + wn + nt * 8 + qc;
            const float2 bb = *(const float2*)(bias + col);
            float2 v0, v1;
            v0.x = acc[mt][nt][0] + bb.x; v0.y = acc[mt][nt][1] + bb.y;
            v1.x = acc[mt][nt][2] + bb.x; v1.y = acc[mt][nt][3] + bb.y;
            if (mode == 1) { v0.x *= cf0; v0.y *= cf0; v1.x *= cf1; v1.y *= cf1; }
            if (mode == 2) {
                const float2 a10 = *(const float2*)(add1 + (long)r0 * N + col);
                const float2 a11 = *(const float2*)(add1 + (long)r1 * N + col);
                const float2 a20 = *(const float2*)(add2 + (long)r0 * N + col);
                const float2 a21 = *(const float2*)(add2 + (long)r1 * N + col);
                v0.x += a10.x + a20.x; v0.y += a10.y + a20.y;
                v1.x += a11.x + a21.x; v1.y += a11.y + a21.y;
            }
            *(float2*)(C + (long)r0 * N + col) = v0;
            *(float2*)(C + (long)r1 * N + col) = v1;
        }
    }
}

#define GEMM_SMEM3 (3*4*ARR_STRIDE)   /* 122880 */
#define GEMM_SMEM1 (3*2*ARR_STRIDE)   /* 61440  */

/* ---------------- driver ---------------- */
extern "C" void kernel_launch(void* const* d_in, const int* in_sizes, int n_in,
                              void* d_out, int out_size)
{
    (void)in_sizes; (void)n_in; (void)out_size;
    const int*   tokens = (const int*)  d_in[0];
    const float* embedw = (const float*)d_in[1];
    const float* ln_s   = (const float*)d_in[2];
    const float* ln_b   = (const float*)d_in[3];
    const float* pW     = (const float*)d_in[4];
    const float* pb     = (const float*)d_in[5];
    const float* aW     = (const float*)d_in[6];
    const float* ab     = (const float*)d_in[7];
    const float* vW     = (const float*)d_in[8];
    const float* vb     = (const float*)d_in[9];
    const float* oLNs   = (const float*)d_in[10];
    const float* oLNb   = (const float*)d_in[11];
    const float* oW     = (const float*)d_in[12];
    const float* ob     = (const float*)d_in[13];
    const float* nos    = (const float*)d_in[14];
    const float* nob    = (const float*)d_in[15];
    const float* hW     = (const float*)d_in[16];
    const float* hb     = (const float*)d_in[17];
    float* out = (float*)d_out;

    float *h, *hn, *rn, *val, *ret, *coef, *csum;
    __half *ah, *al, *bh, *bl;
    cudaGetSymbolAddress((void**)&h,    g_h);
    cudaGetSymbolAddress((void**)&hn,   g_hn);
    cudaGetSymbolAddress((void**)&rn,   g_rn);
    cudaGetSymbolAddress((void**)&val,  g_val);
    cudaGetSymbolAddress((void**)&ret,  g_ret);
    cudaGetSymbolAddress((void**)&coef, g_coef);
    cudaGetSymbolAddress((void**)&csum, g_csum);
    cudaGetSymbolAddress((void**)&ah,   g_ah);
    cudaGetSymbolAddress((void**)&al,   g_al);
    cudaGetSymbolAddress((void**)&bh,   g_bh);
    cudaGetSymbolAddress((void**)&bl,   g_bl);

    cudaFuncSetAttribute(hm_gemm_kernel<3>,
                         cudaFuncAttributeMaxDynamicSharedMemorySize, GEMM_SMEM3);
    cudaFuncSetAttribute(hm_gemm_kernel<1>,
                         cudaFuncAttributeMaxDynamicSharedMemorySize, GEMM_SMEM1);

    const int splitBlocks = (NT * Dm) / (256 * 4);

    embed_kernel<<<NT, 128>>>(tokens, embedw, h);

    for (int i = 0; i < NLAYER; i++) {
        ln_kernel<<<NT, 256>>>(h, hn, ln_s + i * Dm, ln_b + i * Dm,
                               pW + (long)i * Dm * Pm, pb + i * Pm,
                               aW + (long)i * Dm * Pm, ab + i * Pm, coef, 1);
        split_kernel<<<splitBlocks, 256>>>(hn, ah, al);
        tsplit_kernel<<<dim3(Dm / 32, Dm / 32), 256>>>(
            vW + (long)i * Dm * Dm, bh, bl, Dm, Dm, 1);
        hm_gemm_kernel<3><<<dim3(Dm / 128, NT / 128), 256, GEMM_SMEM3>>>(
            ah, al, bh, bl, val, NT, Dm, Dm,
            vb + i * Dm, coef, nullptr, nullptr, 1);
        chunk_sum_kernel<<<dim3(NCH, BATCH), Dm>>>(val, csum);
        chunk_scan_kernel<<<dim3(NCH, BATCH), Dm>>>(val, csum, ret);
        ln_kernel<<<NT, 256>>>(ret, rn, oLNs + i * Dm, oLNb + i * Dm,
                               nullptr, nullptr, nullptr, nullptr, nullptr, 0);
        split_kernel<<<splitBlocks, 256>>>(rn, ah, al);
        tsplit_kernel<<<dim3(Dm / 32, Dm / 32), 256>>>(
            oW + (long)i * Dm * Dm, bh, bl, Dm, Dm, 1);
        hm_gemm_kernel<3><<<dim3(Dm / 128, NT / 128), 256, GEMM_SMEM3>>>(
            ah, al, bh, bl, h, NT, Dm, Dm,
            ob + i * Dm, nullptr, h, hn, 2);
    }

    ln_kernel<<<NT, 256>>>(h, hn, nos, nob,
                           nullptr, nullptr, nullptr, nullptr, nullptr, 0);
    split_kernel<<<splitBlocks, 256>>>(hn, ah, al);
    tsplit_kernel<<<dim3(Vm / 32, Dm / 32), 256>>>(hW, bh, bl, Dm, Vm, 0);
    hm_gemm_kernel<1><<<dim3(Vm / 128, NT / 128), 256, GEMM_SMEM1>>>(
        ah, al, bh, bl, out, NT, Vm, Dm,
        hb, nullptr, nullptr, nullptr, 0);
}

// round 11
// speedup vs baseline: 3.1623x; 1.0041x over previous
#include <cuda_runtime.h>
#include <cuda_fp16.h>
#include <math.h>
#include <stdint.h>

#define Dm 512
#define Lm 2048
#define BATCH 2
#define NLAYER 4
#define Pm 8
#define Vm 32000
#define NT (BATCH*Lm)   /* 4096 tokens */
#define NCH 64
#define CHL (Lm/NCH)    /* 32 */

/* ---------------- scratch (no allocation allowed) ---------------- */
__device__ float g_h  [NT*Dm];
__device__ float g_hn [NT*Dm];
__device__ float g_val[NT*Dm];
__device__ float g_ret[NT*Dm];
__device__ float g_coef[NT];
__device__ float g_csum[BATCH*NCH*Dm];
__device__ __half g_ah[NT*Dm];       /* A hi */
__device__ __half g_al[NT*Dm];       /* A lo */
__device__ __half g_bh[(long)Vm*Dm]; /* B^T hi  [N,K] */
__device__ __half g_bl[(long)Vm*Dm]; /* B^T lo  [N,K] */

/* ---------------- PTX helpers (baseline ISA, valid on sm_103) ---------- */
__device__ __forceinline__ uint32_t smem_to_u32(const void* p) {
    uint32_t a;
    asm("{ .reg .u64 t; cvta.to.shared.u64 t, %1; cvt.u32.u64 %0, t; }" : "=r"(a) : "l"(p));
    return a;
}
#define CP_ASYNC16(dst, src) \
    asm volatile("cp.async.cg.shared.global [%0], [%1], 16;" :: "r"(dst), "l"(src))
#define CP_COMMIT() asm volatile("cp.async.commit_group;" ::: "memory")
#define CP_WAIT2()  asm volatile("cp.async.wait_group 2;" ::: "memory")
#define LDSM4(r0, r1, r2, r3, addr) \
    asm volatile("ldmatrix.sync.aligned.m8n8.x4.shared.b16 {%0,%1,%2,%3}, [%4];" \
                 : "=r"(r0), "=r"(r1), "=r"(r2), "=r"(r3) : "r"(addr))
#define MMA16816(d, a, b) \
    asm volatile("mma.sync.aligned.m16n8k16.row.col.f32.f16.f16.f32 " \
                 "{%0,%1,%2,%3}, {%4,%5,%6,%7}, {%8,%9}, {%0,%1,%2,%3};" \
                 : "+f"((d)[0]), "+f"((d)[1]), "+f"((d)[2]), "+f"((d)[3]) \
                 : "r"((a)[0]), "r"((a)[1]), "r"((a)[2]), "r"((a)[3]), \
                   "r"((b)[0]), "r"((b)[1]))

/* ---------------- helpers ---------------- */
__device__ __forceinline__ float warp_sum(float v) {
#pragma unroll
    for (int o = 16; o > 0; o >>= 1) v += __shfl_down_sync(0xffffffffu, v, o);
    return v;
}
__device__ __forceinline__ float softplusf(float x) {
    return (x > 20.f) ? x : log1pf(expf(x));
}

/* ---------------- embedding gather ---------------- */
__global__ void embed_kernel(const int* __restrict__ tok,
                             const float* __restrict__ emb,
                             float* __restrict__ h) {
    const int t = blockIdx.x;
    const int tk = tok[t];
    const float4* s = (const float4*)(emb + (long)tk * Dm);
    float4* d = (float4*)(h + (long)t * Dm);
    d[threadIdx.x] = s[threadIdx.x];
}

/* ---------------- LayerNorm, fused fp16 hi/lo split (+opt coef) --------
 * Y32 (fp32 out), H (fp16 hi), L (fp16 lo) each optional (nullptr skips) */
__global__ void __launch_bounds__(256) ln_kernel(
    const float* __restrict__ X, float* __restrict__ Y32,
    __half* __restrict__ H, __half* __restrict__ L,
    const float* __restrict__ gamma, const float* __restrict__ beta,
    const float* __restrict__ pW, const float* __restrict__ pb,
    const float* __restrict__ aW, const float* __restrict__ ab,
    float* __restrict__ coef, int docoef)
{
    const int t = blockIdx.x;
    const int tid = threadIdx.x;
    const int w = tid >> 5, lane = tid & 31;

    const float2 v = ((const float2*)(X + (long)t * Dm))[tid];
    float s  = v.x + v.y;
    float ss = v.x * v.x + v.y * v.y;

    __shared__ float sred[2][8];
    __shared__ float smean, sinv;
    float ws = warp_sum(s), wss = warp_sum(ss);
    if (lane == 0) { sred[0][w] = ws; sred[1][w] = wss; }
    __syncthreads();
    if (tid == 0) {
        float S = 0.f, SS = 0.f;
#pragma unroll
        for (int i = 0; i < 8; i++) { S += sred[0][i]; SS += sred[1][i]; }
        const float m = S * (1.f / Dm);
        const float var = SS * (1.f / Dm) - m * m;
        smean = m; sinv = rsqrtf(var + 1e-5f);
    }
    __syncthreads();
    const float m = smean, inv = sinv;
    const int d0 = tid * 2;
    const float y0 = (v.x - m) * inv * gamma[d0]     + beta[d0];
    const float y1 = (v.y - m) * inv * gamma[d0 + 1] + beta[d0 + 1];
    if (Y32) ((float2*)(Y32 + (long)t * Dm))[tid] = make_float2(y0, y1);
    if (H) {
        const __half h0 = __float2half_rn(y0), h1 = __float2half_rn(y1);
        ((__half2*)(H + (long)t * Dm))[tid] = __halves2half2(h0, h1);
        if (L) {
            const __half l0 = __float2half_rn(y0 - __half2float(h0));
            const __half l1 = __float2half_rn(y1 - __half2float(h1));
            ((__half2*)(L + (long)t * Dm))[tid] = __halves2half2(l0, l1);
        }
    }

    if (docoef) {
        float pa[8], aa[8];
#pragma unroll
        for (int j = 0; j < 8; j++) { pa[j] = 0.f; aa[j] = 0.f; }
        const float4* pw4 = (const float4*)(pW + (long)d0 * Pm);
        const float4* aw4 = (const float4*)(aW + (long)d0 * Pm);
        const float ys[2] = { y0, y1 };
#pragma unroll
        for (int dd = 0; dd < 2; dd++) {
            const float yv = ys[dd];
            float4 w0 = pw4[dd * 2], w1 = pw4[dd * 2 + 1];
            pa[0] += yv * w0.x; pa[1] += yv * w0.y; pa[2] += yv * w0.z; pa[3] += yv * w0.w;
            pa[4] += yv * w1.x; pa[5] += yv * w1.y; pa[6] += yv * w1.z; pa[7] += yv * w1.w;
            w0 = aw4[dd * 2]; w1 = aw4[dd * 2 + 1];
            aa[0] += yv * w0.x; aa[1] += yv * w0.y; aa[2] += yv * w0.z; aa[3] += yv * w0.w;
            aa[4] += yv * w1.x; aa[5] += yv * w1.y; aa[6] += yv * w1.z; aa[7] += yv * w1.w;
        }
        __shared__ float red16[16][8];
#pragma unroll
        for (int j = 0; j < 8; j++) {
            float r = warp_sum(pa[j]); if (lane == 0) red16[j][w] = r;
            r = warp_sum(aa[j]);       if (lane == 0) red16[8 + j][w] = r;
        }
        __syncthreads();
        if (tid < 16) {
            float r = 0.f;
#pragma unroll
            for (int i = 0; i < 8; i++) r += red16[tid][i];
            red16[tid][0] = r;
        }
        __syncthreads();
        if (tid == 0) {
            float c = 0.f;
#pragma unroll
            for (int p = 0; p < 8; p++) {
                const float ph = tanhf(red16[p][0] + pb[p]) * 3.14159265358979323846f;
                const float am = softplusf(red16[8 + p][0] + ab[p]) + 0.1f;
                c += am * (cosf(ph) + sinf(ph));
            }
            coef[t] = c;
        }
    }
}

/* ---------------- chunked cumulative sum over L ---------------- */
__global__ void chunk_sum_kernel(const float* __restrict__ val,
                                 float* __restrict__ csum) {
    const int c = blockIdx.x, b = blockIdx.y, d = threadIdx.x;
    const float* p = val + ((long)(b * Lm + c * CHL)) * Dm + d;
    float s = 0.f;
#pragma unroll 8
    for (int l = 0; l < CHL; l++) s += p[(long)l * Dm];
    csum[(b * NCH + c) * Dm + d] = s;
}

__global__ void chunk_scan_kernel(const float* __restrict__ val,
                                  const float* __restrict__ csum,
                                  float* __restrict__ ret) {
    const int c = blockIdx.x, b = blockIdx.y, d = threadIdx.x;
    float run = 0.f;
    for (int cc = 0; cc < c; cc++) run += csum[(b * NCH + cc) * Dm + d];
    const float* p = val + ((long)(b * Lm + c * CHL)) * Dm + d;
    float* q       = ret + ((long)(b * Lm + c * CHL)) * Dm + d;
    const float sc = 0.022097086912079608f;   /* 1/sqrt(2048) */
#pragma unroll 8
    for (int l = 0; l < CHL; l++) { run += p[(long)l * Dm]; q[(long)l * Dm] = run * sc; }
}

/* ---------------- transpose + split: W[K,N] fp32 -> Bt[N,K] fp16 hi/lo - */
__global__ void __launch_bounds__(256) tsplit_kernel(
    const float* __restrict__ W,
    __half* __restrict__ Bh, __half* __restrict__ Bl,
    int K, int N, int wantlo)
{
    __shared__ float tile[32][33];
    const int n0 = blockIdx.x * 32, k0 = blockIdx.y * 32;
    const int c = threadIdx.x & 31, r0 = threadIdx.x >> 5;
#pragma unroll
    for (int i = 0; i < 4; i++) {
        const int r = r0 + i * 8;
        tile[r][c] = W[(long)(k0 + r) * N + n0 + c];
    }
    __syncthreads();
#pragma unroll
    for (int i = 0; i < 4; i++) {
        const int r = r0 + i * 8;            /* n index within tile */
        const float v = tile[c][r];
        const __half h = __float2half_rn(v);
        const long o = (long)(n0 + r) * K + k0 + c;
        Bh[o] = h;
        if (wantlo) Bl[o] = __float2half_rn(v - __half2float(h));
    }
}

/* ---------------- warp-MMA GEMM: C[M,N] = A[M,K] @ Bt[N,K]^T ------------
 * NPASS==3: C = Ah*Bh + Al*Bh + Ah*Bl    NPASS==1: C = Ah*Bh
 * CTA tile MTILE x 128, 8 warps, K-tile 32, 3-stage cp.async pipeline.
 * blockIdx.x = M-tile (A stays L2-resident; B streamed once on head GEMM).
 * SMEM row pitch 80 B -> conflict-free ldmatrix.
 * mode 0: +bias; 1: (x+bias)*coef[m]; 2: +bias+add1+add2                 */
template<int NPASS, int MTILE>
__global__ void __launch_bounds__(256) hm_gemm_kernel(
    const __half* __restrict__ Ah, const __half* __restrict__ Al,
    const __half* __restrict__ Bh, const __half* __restrict__ Bl,
    float* __restrict__ C, int M, int N, int K,
    const float* __restrict__ bias, const float* __restrict__ coef,
    const float* __restrict__ add1, const float* __restrict__ add2,
    int mode)
{
    constexpr int NA = (NPASS == 3) ? 2 : 1;
    constexpr int NB = (NPASS == 3) ? 2 : 1;
    constexpr uint32_t A_STRIDE = (uint32_t)MTILE * 80u;
    constexpr uint32_t B_STRIDE = 10240u;           /* 128 rows x 80B */
    constexpr uint32_t BHOFF = NA * A_STRIDE;
    constexpr uint32_t STG = NA * A_STRIDE + NB * B_STRIDE;
    constexpr int WMT = MTILE / 32;                  /* mt count per warp */

    extern __shared__ char smem[];
    const uint32_t sbase = smem_to_u32(smem);
    const int tid = threadIdx.x;
    const int wid = tid >> 5, lane = tid & 31;
    const int m0 = blockIdx.x * MTILE;
    const int n0 = blockIdx.y * 128;
    const int wm = (wid >> 2) * (MTILE / 2);
    const int wn = (wid & 3) * 32;
    const int nkt = K >> 5;

    float acc[WMT][4][4];
#pragma unroll
    for (int i = 0; i < WMT; i++)
#pragma unroll
        for (int j = 0; j < 4; j++)
#pragma unroll
            for (int q = 0; q < 4; q++) acc[i][j][q] = 0.f;

    auto load_stage = [&](int buf, int kt) {
        const int kbase = kt * 32;
        const uint32_t dstb = sbase + (uint32_t)buf * STG;
#pragma unroll
        for (int a = 0; a < NA; a++) {
            const __half* src = a ? Al : Ah;
            const uint32_t d0 = dstb + a * A_STRIDE;
#pragma unroll
            for (int i = 0; i < MTILE / 64; i++) {
                const int idx = i * 256 + tid;
                const int row = idx >> 2, c = idx & 3;
                CP_ASYNC16(d0 + row * 80 + c * 16,
                           src + (long)(m0 + row) * K + kbase + c * 8);
            }
        }
#pragma unroll
        for (int b = 0; b < NB; b++) {
            const __half* src = b ? Bl : Bh;
            const uint32_t d0 = dstb + BHOFF + b * B_STRIDE;
#pragma unroll
            for (int i = 0; i < 2; i++) {
                const int idx = i * 256 + tid;
                const int row = idx >> 2, c = idx & 3;
                CP_ASYNC16(d0 + row * 80 + c * 16,
                           src + (long)(n0 + row) * K + kbase + c * 8);
            }
        }
    };

    load_stage(0, 0); CP_COMMIT();
    load_stage(1, 1); CP_COMMIT();

    const int mat = lane >> 3, mr = lane & 7;

    for (int kt = 0; kt < nkt; kt++) {
        if (kt + 2 < nkt) load_stage((kt + 2) % 3, kt + 2);
        CP_COMMIT();
        CP_WAIT2();
        __syncthreads();

        const uint32_t base = sbase + (uint32_t)(kt % 3) * STG;
#pragma unroll
        for (int kk = 0; kk < 2; kk++) {
            uint32_t ahf[WMT][4], alf[WMT][4], bhf[4][2], blf[4][2];
#pragma unroll
            for (int pr = 0; pr < 2; pr++) {
                const uint32_t baddr = base + BHOFF
                    + (uint32_t)(wn + pr * 16 + ((mat >> 1) << 3) + mr) * 80
                    + kk * 32 + ((mat & 1) << 4);
                LDSM4(bhf[pr*2][0], bhf[pr*2][1], bhf[pr*2+1][0], bhf[pr*2+1][1], baddr);
                if (NPASS == 3) {
                    LDSM4(blf[pr*2][0], blf[pr*2][1], blf[pr*2+1][0], blf[pr*2+1][1],
                          baddr + B_STRIDE);
                }
            }
#pragma unroll
            for (int mt = 0; mt < WMT; mt++) {
                const uint32_t aoff =
                    (uint32_t)(wm + mt * 16 + ((mat & 1) << 3) + mr) * 80
                    + kk * 32 + ((mat >> 1) << 4);
                LDSM4(ahf[mt][0], ahf[mt][1], ahf[mt][2], ahf[mt][3], base + aoff);
                if (NPASS == 3) {
                    LDSM4(alf[mt][0], alf[mt][1], alf[mt][2], alf[mt][3],
                          base + A_STRIDE + aoff);
                }
            }
#pragma unroll
            for (int mt = 0; mt < WMT; mt++)
#pragma unroll
                for (int nt = 0; nt < 4; nt++) {
                    MMA16816(acc[mt][nt], ahf[mt], bhf[nt]);
                    if (NPASS == 3) {
                        MMA16816(acc[mt][nt], alf[mt], bhf[nt]);
                        MMA16816(acc[mt][nt], ahf[mt], blf[nt]);
                    }
                }
        }
        __syncthreads();
    }

    const int qr = lane >> 2, qc = (lane & 3) * 2;
#pragma unroll
    for (int mt = 0; mt < WMT; mt++) {
        const int r0 = m0 + wm + mt * 16 + qr;
        const int r1 = r0 + 8;
        const float cf0 = (mode == 1) ? coef[r0] : 1.f;
        const float cf1 = (mode == 1) ? coef[r1] : 1.f;
#pragma unroll
        for (int nt = 0; nt < 4; nt++) {
            const int col = n0 + wn + nt * 8 + qc;
            const float2 bb = *(const float2*)(bias + col);
            float2 v0, v1;
            v0.x = acc[mt][nt][0] + bb.x; v0.y = acc[mt][nt][1] + bb.y;
            v1.x = acc[mt][nt][2] + bb.x; v1.y = acc[mt][nt][3] + bb.y;
            if (mode == 1) { v0.x *= cf0; v0.y *= cf0; v1.x *= cf1; v1.y *= cf1; }
            if (mode == 2) {
                const float2 a10 = *(const float2*)(add1 + (long)r0 * N + col);
                const float2 a11 = *(const float2*)(add1 + (long)r1 * N + col);
                const float2 a20 = *(const float2*)(add2 + (long)r0 * N + col);
                const float2 a21 = *(const float2*)(add2 + (long)r1 * N + col);
                v0.x += a10.x + a20.x; v0.y += a10.y + a20.y;
                v1.x += a11.x + a21.x; v1.y += a11.y + a21.y;
            }
            *(float2*)(C + (long)r0 * N + col) = v0;
            *(float2*)(C + (long)r1 * N + col) = v1;
        }
    }
}

#define GEMM_SMEM3_64  (3*(2*64*80u + 2*10240u))   /* 92160 -> 2 CTAs/SM */
#define GEMM_SMEM1_128 (3*(128*80u + 10240u))      /* 61440 -> 3 CTAs/SM */

/* ---------------- driver ---------------- */
extern "C" void kernel_launch(void* const* d_in, const int* in_sizes, int n_in,
                              void* d_out, int out_size)
{
    (void)in_sizes; (void)n_in; (void)out_size;
    const int*   tokens = (const int*)  d_in[0];
    const float* embedw = (const float*)d_in[1];
    const float* ln_s   = (const float*)d_in[2];
    const float* ln_b   = (const float*)d_in[3];
    const float* pW     = (const float*)d_in[4];
    const float* pb     = (const float*)d_in[5];
    const float* aW     = (const float*)d_in[6];
    const float* ab     = (const float*)d_in[7];
    const float* vW     = (const float*)d_in[8];
    const float* vb     = (const float*)d_in[9];
    const float* oLNs   = (const float*)d_in[10];
    const float* oLNb   = (const float*)d_in[11];
    const float* oW     = (const float*)d_in[12];
    const float* ob     = (const float*)d_in[13];
    const float* nos    = (const float*)d_in[14];
    const float* nob    = (const float*)d_in[15];
    const float* hW     = (const float*)d_in[16];
    const float* hb     = (const float*)d_in[17];
    float* out = (float*)d_out;

    float *h, *hn, *val, *ret, *coef, *csum;
    __half *ah, *al, *bh, *bl;
    cudaGetSymbolAddress((void**)&h,    g_h);
    cudaGetSymbolAddress((void**)&hn,   g_hn);
    cudaGetSymbolAddress((void**)&val,  g_val);
    cudaGetSymbolAddress((void**)&ret,  g_ret);
    cudaGetSymbolAddress((void**)&coef, g_coef);
    cudaGetSymbolAddress((void**)&csum, g_csum);
    cudaGetSymbolAddress((void**)&ah,   g_ah);
    cudaGetSymbolAddress((void**)&al,   g_al);
    cudaGetSymbolAddress((void**)&bh,   g_bh);
    cudaGetSymbolAddress((void**)&bl,   g_bl);

    cudaFuncSetAttribute((const void*)hm_gemm_kernel<3, 64>,
                         cudaFuncAttributeMaxDynamicSharedMemorySize, GEMM_SMEM3_64);
    cudaFuncSetAttribute((const void*)hm_gemm_kernel<1, 128>,
                         cudaFuncAttributeMaxDynamicSharedMemorySize, GEMM_SMEM1_128);

    embed_kernel<<<NT, 128>>>(tokens, embedw, h);

    for (int i = 0; i < NLAYER; i++) {
        /* LN + coef + fused split (hn fp32 kept: residual add2 input) */
        ln_kernel<<<NT, 256>>>(h, hn, ah, al, ln_s + i * Dm, ln_b + i * Dm,
                               pW + (long)i * Dm * Pm, pb + i * Pm,
                               aW + (long)i * Dm * Pm, ab + i * Pm, coef, 1);
        tsplit_kernel<<<dim3(Dm / 32, Dm / 32), 256>>>(
            vW + (long)i * Dm * Dm, bh, bl, Dm, Dm, 1);
        hm_gemm_kernel<3, 64><<<dim3(NT / 64, Dm / 128), 256, GEMM_SMEM3_64>>>(
            ah, al, bh, bl, val, NT, Dm, Dm,
            vb + i * Dm, coef, nullptr, nullptr, 1);
        chunk_sum_kernel<<<dim3(NCH, BATCH), Dm>>>(val, csum);
        chunk_scan_kernel<<<dim3(NCH, BATCH), Dm>>>(val, csum, ret);
        /* out-LN: no fp32 output needed, only fp16 hi/lo */
        ln_kernel<<<NT, 256>>>(ret, nullptr, ah, al, oLNs + i * Dm, oLNb + i * Dm,
                               nullptr, nullptr, nullptr, nullptr, nullptr, 0);
        tsplit_kernel<<<dim3(Dm / 32, Dm / 32), 256>>>(
            oW + (long)i * Dm * Dm, bh, bl, Dm, Dm, 1);
        hm_gemm_kernel<3, 64><<<dim3(NT / 64, Dm / 128), 256, GEMM_SMEM3_64>>>(
            ah, al, bh, bl, h, NT, Dm, Dm,
            ob + i * Dm, nullptr, h, hn, 2);
    }

    /* final LN: head GEMM is 1-pass, only fp16 hi needed */
    ln_kernel<<<NT, 256>>>(h, nullptr, ah, nullptr, nos, nob,
                           nullptr, nullptr, nullptr, nullptr, nullptr, 0);
    tsplit_kernel<<<dim3(Vm / 32, Dm / 32), 256>>>(hW, bh, bl, Dm, Vm, 0);
    hm_gemm_kernel<1, 128><<<dim3(NT / 128, Vm / 128), 256, GEMM_SMEM1_128>>>(
        ah, al, bh, bl, out, NT, Vm, Dm,
        hb, nullptr, nullptr, nullptr, 0);
}

// round 14
// speedup vs baseline: 3.3175x; 1.0491x over previous
#include <cuda_runtime.h>
#include <cuda_fp16.h>
#include <math.h>
#include <stdint.h>

#define Dm 512
#define Lm 2048
#define BATCH 2
#define NLAYER 4
#define Pm 8
#define Vm 32000
#define NT (BATCH*Lm)   /* 4096 tokens */
#define NCH 64
#define CHL (Lm/NCH)    /* 32 */

/* ---------------- scratch (no allocation allowed) ---------------- */
__device__ float g_h  [NT*Dm];
__device__ float g_hn [NT*Dm];
__device__ float g_val[NT*Dm];
__device__ float g_coef[NT];
__device__ float g_csum[BATCH*NCH*Dm];
__device__ __half g_ah[NT*Dm];       /* A hi */
__device__ __half g_al[NT*Dm];       /* A lo */
__device__ __half g_bh[(long)Vm*Dm]; /* B^T hi  [N,K] */
__device__ __half g_bl[(long)Vm*Dm]; /* B^T lo  [N,K] */

/* ---------------- PTX helpers (baseline ISA, valid on sm_103) ---------- */
__device__ __forceinline__ uint32_t smem_to_u32(const void* p) {
    uint32_t a;
    asm("{ .reg .u64 t; cvta.to.shared.u64 t, %1; cvt.u32.u64 %0, t; }" : "=r"(a) : "l"(p));
    return a;
}
#define CP_ASYNC16(dst, src) \
    asm volatile("cp.async.cg.shared.global [%0], [%1], 16;" :: "r"(dst), "l"(src))
#define CP_COMMIT() asm volatile("cp.async.commit_group;" ::: "memory")
#define CP_WAIT1()  asm volatile("cp.async.wait_group 1;" ::: "memory")
#define LDSM4(r0, r1, r2, r3, addr) \
    asm volatile("ldmatrix.sync.aligned.m8n8.x4.shared.b16 {%0,%1,%2,%3}, [%4];" \
                 : "=r"(r0), "=r"(r1), "=r"(r2), "=r"(r3) : "r"(addr))
#define MMA16816(d, a, b) \
    asm volatile("mma.sync.aligned.m16n8k16.row.col.f32.f16.f16.f32 " \
                 "{%0,%1,%2,%3}, {%4,%5,%6,%7}, {%8,%9}, {%0,%1,%2,%3};" \
                 : "+f"((d)[0]), "+f"((d)[1]), "+f"((d)[2]), "+f"((d)[3]) \
                 : "r"((a)[0]), "r"((a)[1]), "r"((a)[2]), "r"((a)[3]), \
                   "r"((b)[0]), "r"((b)[1]))

/* ---------------- helpers ---------------- */
__device__ __forceinline__ float warp_sum(float v) {
#pragma unroll
    for (int o = 16; o > 0; o >>= 1) v += __shfl_down_sync(0xffffffffu, v, o);
    return v;
}
__device__ __forceinline__ float warp_sum_xor(float v) {
#pragma unroll
    for (int o = 16; o > 0; o >>= 1) v += __shfl_xor_sync(0xffffffffu, v, o);
    return v;
}
__device__ __forceinline__ float softplusf(float x) {
    return (x > 20.f) ? x : log1pf(expf(x));
}

/* ---------------- embedding gather ---------------- */
__global__ void embed_kernel(const int* __restrict__ tok,
                             const float* __restrict__ emb,
                             float* __restrict__ h) {
    const int t = blockIdx.x;
    const int tk = tok[t];
    const float4* s = (const float4*)(emb + (long)tk * Dm);
    float4* d = (float4*)(h + (long)t * Dm);
    d[threadIdx.x] = s[threadIdx.x];
}

/* ---------------- LayerNorm, fused fp16 hi/lo split (+opt coef) --------
 * Y32 (fp32 out), H (fp16 hi), L (fp16 lo) each optional (nullptr skips) */
__global__ void __launch_bounds__(256) ln_kernel(
    const float* __restrict__ X, float* __restrict__ Y32,
    __half* __restrict__ H, __half* __restrict__ L,
    const float* __restrict__ gamma, const float* __restrict__ beta,
    const float* __restrict__ pW, const float* __restrict__ pb,
    const float* __restrict__ aW, const float* __restrict__ ab,
    float* __restrict__ coef, int docoef)
{
    const int t = blockIdx.x;
    const int tid = threadIdx.x;
    const int w = tid >> 5, lane = tid & 31;

    const float2 v = ((const float2*)(X + (long)t * Dm))[tid];
    float s  = v.x + v.y;
    float ss = v.x * v.x + v.y * v.y;

    __shared__ float sred[2][8];
    __shared__ float smean, sinv;
    float ws = warp_sum(s), wss = warp_sum(ss);
    if (lane == 0) { sred[0][w] = ws; sred[1][w] = wss; }
    __syncthreads();
    if (tid == 0) {
        float S = 0.f, SS = 0.f;
#pragma unroll
        for (int i = 0; i < 8; i++) { S += sred[0][i]; SS += sred[1][i]; }
        const float m = S * (1.f / Dm);
        const float var = SS * (1.f / Dm) - m * m;
        smean = m; sinv = rsqrtf(var + 1e-5f);
    }
    __syncthreads();
    const float m = smean, inv = sinv;
    const int d0 = tid * 2;
    const float y0 = (v.x - m) * inv * gamma[d0]     + beta[d0];
    const float y1 = (v.y - m) * inv * gamma[d0 + 1] + beta[d0 + 1];
    if (Y32) ((float2*)(Y32 + (long)t * Dm))[tid] = make_float2(y0, y1);
    if (H) {
        const __half h0 = __float2half_rn(y0), h1 = __float2half_rn(y1);
        ((__half2*)(H + (long)t * Dm))[tid] = __halves2half2(h0, h1);
        if (L) {
            const __half l0 = __float2half_rn(y0 - __half2float(h0));
            const __half l1 = __float2half_rn(y1 - __half2float(h1));
            ((__half2*)(L + (long)t * Dm))[tid] = __halves2half2(l0, l1);
        }
    }

    if (docoef) {
        float pa[8], aa[8];
#pragma unroll
        for (int j = 0; j < 8; j++) { pa[j] = 0.f; aa[j] = 0.f; }
        const float4* pw4 = (const float4*)(pW + (long)d0 * Pm);
        const float4* aw4 = (const float4*)(aW + (long)d0 * Pm);
        const float ys[2] = { y0, y1 };
#pragma unroll
        for (int dd = 0; dd < 2; dd++) {
            const float yv = ys[dd];
            float4 w0 = pw4[dd * 2], w1 = pw4[dd * 2 + 1];
            pa[0] += yv * w0.x; pa[1] += yv * w0.y; pa[2] += yv * w0.z; pa[3] += yv * w0.w;
            pa[4] += yv * w1.x; pa[5] += yv * w1.y; pa[6] += yv * w1.z; pa[7] += yv * w1.w;
            w0 = aw4[dd * 2]; w1 = aw4[dd * 2 + 1];
            aa[0] += yv * w0.x; aa[1] += yv * w0.y; aa[2] += yv * w0.z; aa[3] += yv * w0.w;
            aa[4] += yv * w1.x; aa[5] += yv * w1.y; aa[6] += yv * w1.z; aa[7] += yv * w1.w;
        }
        __shared__ float red16[16][8];
#pragma unroll
        for (int j = 0; j < 8; j++) {
            float r = warp_sum(pa[j]); if (lane == 0) red16[j][w] = r;
            r = warp_sum(aa[j]);       if (lane == 0) red16[8 + j][w] = r;
        }
        __syncthreads();
        if (tid < 16) {
            float r = 0.f;
#pragma unroll
            for (int i = 0; i < 8; i++) r += red16[tid][i];
            red16[tid][0] = r;
        }
        __syncthreads();
        if (tid == 0) {
            float c = 0.f;
#pragma unroll
            for (int p = 0; p < 8; p++) {
                const float ph = tanhf(red16[p][0] + pb[p]) * 3.14159265358979323846f;
                const float am = softplusf(red16[8 + p][0] + ab[p]) + 0.1f;
                c += am * (cosf(ph) + sinf(ph));
            }
            coef[t] = c;
        }
    }
}

/* ---------------- fused scan + out-LN + fp16 split ----------------------
 * block (chunk c, batch b), 512 threads. Phase 1: cumulative scan of val
 * over this chunk's 32 tokens into SMEM (scaled). Phase 2: 16 warps do
 * LayerNorm of 2 tokens each, write fp16 hi/lo A operands.               */
__global__ void __launch_bounds__(512) scan_ln_kernel(
    const float* __restrict__ val, const float* __restrict__ csum,
    __half* __restrict__ H, __half* __restrict__ L,
    const float* __restrict__ gamma, const float* __restrict__ beta)
{
    extern __shared__ float sm[];          /* [CHL][Dm] = 32 x 512 */
    const int c = blockIdx.x, b = blockIdx.y;
    const int tid = threadIdx.x;

    float run = 0.f;
    for (int cc = 0; cc < c; cc++) run += csum[(b * NCH + cc) * Dm + tid];
    const float sc = 0.022097086912079608f;   /* 1/sqrt(2048) */
    const float* p = val + ((long)(b * Lm + c * CHL)) * Dm + tid;
#pragma unroll
    for (int l = 0; l < CHL; l++) {
        run += p[(long)l * Dm];
        sm[l * Dm + tid] = run * sc;
    }
    __syncthreads();

    const int w = tid >> 5, lane = tid & 31;
#pragma unroll
    for (int u = 0; u < 2; u++) {
        const int tt = w * 2 + u;
        float x[16];
        float s = 0.f, ss = 0.f;
#pragma unroll
        for (int i = 0; i < 16; i++) {
            x[i] = sm[tt * Dm + lane + 32 * i];
            s += x[i]; ss += x[i] * x[i];
        }
        s = warp_sum_xor(s); ss = warp_sum_xor(ss);
        const float mean = s * (1.f / Dm);
        const float var = ss * (1.f / Dm) - mean * mean;
        const float inv = rsqrtf(var + 1e-5f);
        const long t = (long)(b * Lm + c * CHL + tt);
#pragma unroll
        for (int i = 0; i < 16; i++) {
            const int d = lane + 32 * i;
            const float y = (x[i] - mean) * inv * gamma[d] + beta[d];
            const __half h = __float2half_rn(y);
            H[t * Dm + d] = h;
            L[t * Dm + d] = __float2half_rn(y - __half2float(h));
        }
    }
}

/* ---------------- transpose + split: W[K,N] fp32 -> Bt[N,K] fp16 hi/lo - */
__global__ void __launch_bounds__(256) tsplit_kernel(
    const float* __restrict__ W,
    __half* __restrict__ Bh, __half* __restrict__ Bl,
    int K, int N, int wantlo)
{
    __shared__ float tile[32][33];
    const int n0 = blockIdx.x * 32, k0 = blockIdx.y * 32;
    const int c = threadIdx.x & 31, r0 = threadIdx.x >> 5;
#pragma unroll
    for (int i = 0; i < 4; i++) {
        const int r = r0 + i * 8;
        tile[r][c] = W[(long)(k0 + r) * N + n0 + c];
    }
    __syncthreads();
#pragma unroll
    for (int i = 0; i < 4; i++) {
        const int r = r0 + i * 8;            /* n index within tile */
        const float v = tile[c][r];
        const __half h = __float2half_rn(v);
        const long o = (long)(n0 + r) * K + k0 + c;
        Bh[o] = h;
        if (wantlo) Bl[o] = __float2half_rn(v - __half2float(h));
    }
}

/* ---------------- warp-MMA GEMM: C[M,N] = A[M,K] @ Bt[N,K]^T ------------
 * NPASS==3: C = Ah*Bh + Al*Bh + Ah*Bl    NPASS==1: C = Ah*Bh
 * CTA tile MTILE x 128, 8 warps, K-tile 32, 3-stage cp.async pipeline
 * (wait -> sync -> prefetch -> compute; race-free, one sync per iter).
 * mode 0: +bias; 1: (x+bias)*coef[m], + per-chunk column sums -> csum;
 * 2: +bias+add1+add2                                                     */
template<int NPASS, int MTILE>
__global__ void __launch_bounds__(256) hm_gemm_kernel(
    const __half* __restrict__ Ah, const __half* __restrict__ Al,
    const __half* __restrict__ Bh, const __half* __restrict__ Bl,
    float* __restrict__ C, int M, int N, int K,
    const float* __restrict__ bias, const float* __restrict__ coef,
    const float* __restrict__ add1, const float* __restrict__ add2,
    float* __restrict__ csum, int mode)
{
    constexpr int NA = (NPASS == 3) ? 2 : 1;
    constexpr int NB = (NPASS == 3) ? 2 : 1;
    constexpr uint32_t A_STRIDE = (uint32_t)MTILE * 80u;
    constexpr uint32_t B_STRIDE = 10240u;           /* 128 rows x 80B */
    constexpr uint32_t BHOFF = NA * A_STRIDE;
    constexpr uint32_t STG = NA * A_STRIDE + NB * B_STRIDE;
    constexpr int WMT = MTILE / 32;                  /* mt count per warp */

    extern __shared__ char smem[];
    const uint32_t sbase = smem_to_u32(smem);
    const int tid = threadIdx.x;
    const int wid = tid >> 5, lane = tid & 31;
    const int m0 = blockIdx.x * MTILE;
    const int n0 = blockIdx.y * 128;
    const int wm = (wid >> 2) * (MTILE / 2);
    const int wn = (wid & 3) * 32;
    const int nkt = K >> 5;

    float acc[WMT][4][4];
#pragma unroll
    for (int i = 0; i < WMT; i++)
#pragma unroll
        for (int j = 0; j < 4; j++)
#pragma unroll
            for (int q = 0; q < 4; q++) acc[i][j][q] = 0.f;

    auto load_stage = [&](int buf, int kt) {
        const int kbase = kt * 32;
        const uint32_t dstb = sbase + (uint32_t)buf * STG;
#pragma unroll
        for (int a = 0; a < NA; a++) {
            const __half* src = a ? Al : Ah;
            const uint32_t d0 = dstb + a * A_STRIDE;
#pragma unroll
            for (int i = 0; i < MTILE / 64; i++) {
                const int idx = i * 256 + tid;
                const int row = idx >> 2, c = idx & 3;
                CP_ASYNC16(d0 + row * 80 + c * 16,
                           src + (long)(m0 + row) * K + kbase + c * 8);
            }
        }
#pragma unroll
        for (int b = 0; b < NB; b++) {
            const __half* src = b ? Bl : Bh;
            const uint32_t d0 = dstb + BHOFF + b * B_STRIDE;
#pragma unroll
            for (int i = 0; i < 2; i++) {
                const int idx = i * 256 + tid;
                const int row = idx >> 2, c = idx & 3;
                CP_ASYNC16(d0 + row * 80 + c * 16,
                           src + (long)(n0 + row) * K + kbase + c * 8);
            }
        }
    };

    load_stage(0, 0); CP_COMMIT();
    load_stage(1, 1); CP_COMMIT();

    const int mat = lane >> 3, mr = lane & 7;

    for (int kt = 0; kt < nkt; kt++) {
        CP_WAIT1();            /* stage kt landed */
        __syncthreads();       /* separates prior reads from prefetch below */
        if (kt + 2 < nkt) load_stage((kt + 2) % 3, kt + 2);
        CP_COMMIT();

        const uint32_t base = sbase + (uint32_t)(kt % 3) * STG;
#pragma unroll
        for (int kk = 0; kk < 2; kk++) {
            uint32_t ahf[WMT][4], alf[WMT][4], bhf[4][2], blf[4][2];
#pragma unroll
            for (int pr = 0; pr < 2; pr++) {
                const uint32_t baddr = base + BHOFF
                    + (uint32_t)(wn + pr * 16 + ((mat >> 1) << 3) + mr) * 80
                    + kk * 32 + ((mat & 1) << 4);
                LDSM4(bhf[pr*2][0], bhf[pr*2][1], bhf[pr*2+1][0], bhf[pr*2+1][1], baddr);
                if (NPASS == 3) {
                    LDSM4(blf[pr*2][0], blf[pr*2][1], blf[pr*2+1][0], blf[pr*2+1][1],
                          baddr + B_STRIDE);
                }
            }
#pragma unroll
            for (int mt = 0; mt < WMT; mt++) {
                const uint32_t aoff =
                    (uint32_t)(wm + mt * 16 + ((mat & 1) << 3) + mr) * 80
                    + kk * 32 + ((mat >> 1) << 4);
                LDSM4(ahf[mt][0], ahf[mt][1], ahf[mt][2], ahf[mt][3], base + aoff);
                if (NPASS == 3) {
                    LDSM4(alf[mt][0], alf[mt][1], alf[mt][2], alf[mt][3],
                          base + A_STRIDE + aoff);
                }
            }
#pragma unroll
            for (int mt = 0; mt < WMT; mt++)
#pragma unroll
                for (int nt = 0; nt < 4; nt++) {
                    MMA16816(acc[mt][nt], ahf[mt], bhf[nt]);
                    if (NPASS == 3) {
                        MMA16816(acc[mt][nt], alf[mt], bhf[nt]);
                        MMA16816(acc[mt][nt], ahf[mt], blf[nt]);
                    }
                }
        }
    }

    const int qr = lane >> 2, qc = (lane & 3) * 2;
    float cs0[4], cs1[4];
#pragma unroll
    for (int nt = 0; nt < 4; nt++) { cs0[nt] = 0.f; cs1[nt] = 0.f; }

#pragma unroll
    for (int mt = 0; mt < WMT; mt++) {
        const int r0 = m0 + wm + mt * 16 + qr;
        const int r1 = r0 + 8;
        const float cf0 = (mode == 1) ? coef[r0] : 1.f;
        const float cf1 = (mode == 1) ? coef[r1] : 1.f;
#pragma unroll
        for (int nt = 0; nt < 4; nt++) {
            const int col = n0 + wn + nt * 8 + qc;
            const float2 bb = *(const float2*)(bias + col);
            float2 v0, v1;
            v0.x = acc[mt][nt][0] + bb.x; v0.y = acc[mt][nt][1] + bb.y;
            v1.x = acc[mt][nt][2] + bb.x; v1.y = acc[mt][nt][3] + bb.y;
            if (mode == 1) {
                v0.x *= cf0; v0.y *= cf0; v1.x *= cf1; v1.y *= cf1;
                cs0[nt] += v0.x + v1.x; cs1[nt] += v0.y + v1.y;
            }
            if (mode == 2) {
                const float2 a10 = *(const float2*)(add1 + (long)r0 * N + col);
                const float2 a11 = *(const float2*)(add1 + (long)r1 * N + col);
                const float2 a20 = *(const float2*)(add2 + (long)r0 * N + col);
                const float2 a21 = *(const float2*)(add2 + (long)r1 * N + col);
                v0.x += a10.x + a20.x; v0.y += a10.y + a20.y;
                v1.x += a11.x + a21.x; v1.y += a11.y + a21.y;
            }
            *(float2*)(C + (long)r0 * N + col) = v0;
            *(float2*)(C + (long)r1 * N + col) = v1;
        }
    }

    if (mode == 1 && MTILE == 64) {
        /* warp rows (m0+wm .. +31) are exactly one 32-token chunk */
        const int rb = m0 + wm;
        const int b = rb >> 11;               /* / Lm */
        const int ch = (rb & (Lm - 1)) >> 5;  /* /32 within batch */
#pragma unroll
        for (int nt = 0; nt < 4; nt++) {
            float a = cs0[nt], bsum = cs1[nt];
#pragma unroll
            for (int off = 16; off >= 4; off >>= 1) {
                a    += __shfl_down_sync(0xffffffffu, a, off);
                bsum += __shfl_down_sync(0xffffffffu, bsum, off);
            }
            if (lane < 4) {
                const int col = n0 + wn + nt * 8 + lane * 2;
                float* dst = csum + (long)(b * NCH + ch) * Dm + col;
                dst[0] = a; dst[1] = bsum;
            }
        }
    }
}

#define GEMM_SMEM3_64  (3*(2*64*80u + 2*10240u))   /* 92160 -> 2 CTAs/SM */
#define GEMM_SMEM1_128 (3*(128*80u + 10240u))      /* 61440 -> 3 CTAs/SM */
#define SCAN_SMEM      (CHL*Dm*4)                  /* 65536 */

/* ---------------- driver ---------------- */
extern "C" void kernel_launch(void* const* d_in, const int* in_sizes, int n_in,
                              void* d_out, int out_size)
{
    (void)in_sizes; (void)n_in; (void)out_size;
    const int*   tokens = (const int*)  d_in[0];
    const float* embedw = (const float*)d_in[1];
    const float* ln_s   = (const float*)d_in[2];
    const float* ln_b   = (const float*)d_in[3];
    const float* pW     = (const float*)d_in[4];
    const float* pb     = (const float*)d_in[5];
    const float* aW     = (const float*)d_in[6];
    const float* ab     = (const float*)d_in[7];
    const float* vW     = (const float*)d_in[8];
    const float* vb     = (const float*)d_in[9];
    const float* oLNs   = (const float*)d_in[10];
    const float* oLNb   = (const float*)d_in[11];
    const float* oW     = (const float*)d_in[12];
    const float* ob     = (const float*)d_in[13];
    const float* nos    = (const float*)d_in[14];
    const float* nob    = (const float*)d_in[15];
    const float* hW     = (const float*)d_in[16];
    const float* hb     = (const float*)d_in[17];
    float* out = (float*)d_out;

    float *h, *hn, *val, *coef, *csum;
    __half *ah, *al, *bh, *bl;
    cudaGetSymbolAddress((void**)&h,    g_h);
    cudaGetSymbolAddress((void**)&hn,   g_hn);
    cudaGetSymbolAddress((void**)&val,  g_val);
    cudaGetSymbolAddress((void**)&coef, g_coef);
    cudaGetSymbolAddress((void**)&csum, g_csum);
    cudaGetSymbolAddress((void**)&ah,   g_ah);
    cudaGetSymbolAddress((void**)&al,   g_al);
    cudaGetSymbolAddress((void**)&bh,   g_bh);
    cudaGetSymbolAddress((void**)&bl,   g_bl);

    cudaFuncSetAttribute((const void*)hm_gemm_kernel<3, 64>,
                         cudaFuncAttributeMaxDynamicSharedMemorySize, GEMM_SMEM3_64);
    cudaFuncSetAttribute((const void*)hm_gemm_kernel<1, 128>,
                         cudaFuncAttributeMaxDynamicSharedMemorySize, GEMM_SMEM1_128);
    cudaFuncSetAttribute((const void*)scan_ln_kernel,
                         cudaFuncAttributeMaxDynamicSharedMemorySize, SCAN_SMEM);

    embed_kernel<<<NT, 128>>>(tokens, embedw, h);

    for (int i = 0; i < NLAYER; i++) {
        /* LN + coef + fused split (hn fp32 kept: residual add2 input) */
        ln_kernel<<<NT, 256>>>(h, hn, ah, al, ln_s + i * Dm, ln_b + i * Dm,
                               pW + (long)i * Dm * Pm, pb + i * Pm,
                               aW + (long)i * Dm * Pm, ab + i * Pm, coef, 1);
        tsplit_kernel<<<dim3(Dm / 32, Dm / 32), 256>>>(
            vW + (long)i * Dm * Dm, bh, bl, Dm, Dm, 1);
        /* value GEMM: writes val and per-chunk column sums (csum) */
        hm_gemm_kernel<3, 64><<<dim3(NT / 64, Dm / 128), 256, GEMM_SMEM3_64>>>(
            ah, al, bh, bl, val, NT, Dm, Dm,
            vb + i * Dm, coef, nullptr, nullptr, csum, 1);
        /* fused chunk-scan + out-LN + fp16 split */
        scan_ln_kernel<<<dim3(NCH, BATCH), 512, SCAN_SMEM>>>(
            val, csum, ah, al, oLNs + i * Dm, oLNb + i * Dm);
        tsplit_kernel<<<dim3(Dm / 32, Dm / 32), 256>>>(
            oW + (long)i * Dm * Dm, bh, bl, Dm, Dm, 1);
        hm_gemm_kernel<3, 64><<<dim3(NT / 64, Dm / 128), 256, GEMM_SMEM3_64>>>(
            ah, al, bh, bl, h, NT, Dm, Dm,
            ob + i * Dm, nullptr, h, hn, nullptr, 2);
    }

    /* final LN: head GEMM is 1-pass, only fp16 hi needed */
    ln_kernel<<<NT, 256>>>(h, nullptr, ah, nullptr, nos, nob,
                           nullptr, nullptr, nullptr, nullptr, nullptr, 0);
    tsplit_kernel<<<dim3(Vm / 32, Dm / 32), 256>>>(hW, bh, bl, Dm, Vm, 0);
    hm_gemm_kernel<1, 128><<<dim3(NT / 128, Vm / 128), 256, GEMM_SMEM1_128>>>(
        ah, al, bh, bl, out, NT, Vm, Dm,
        hb, nullptr, nullptr, nullptr, nullptr, 0);
}